// round 12
// baseline (speedup 1.0000x reference)
#include <cuda_runtime.h>
#include <cuda_bf16.h>
#include <cstdint>

#define BATCH   8
#define SEQ     1024
#define DMODEL  512
#define DINNER  1024
#define DSTATE  16
#define DTRANK  32
#define DCONV   4
#define MTOK    (BATCH*SEQ)
#define NDBC    (DTRANK + 2*DSTATE)

// ---------------- scratch -----------------------------------------------------
__device__ float g_dbcp[4][MTOK * NDBC];
__device__ float g_ylast[BATCH * DINNER];
__device__ float g_last [BATCH * DMODEL];
__device__ float g_lastn[BATCH * DMODEL];
__device__ __nv_bfloat16 g_xh [MTOK * DMODEL];
__device__ __nv_bfloat16 g_xl [MTOK * DMODEL];
__device__ __nv_bfloat16 g_wih[DINNER * DMODEL];
__device__ __nv_bfloat16 g_wil[DINNER * DMODEL];
__device__ __nv_bfloat16 g_wxh[NDBC * DINNER];
__device__ __nv_bfloat16 g_wxl[NDBC * DINNER];
__device__ __nv_bfloat16 g_xch[MTOK * DINNER];
__device__ __nv_bfloat16 g_xcl[MTOK * DINNER];

// ======================= helpers ==============================================
__device__ __forceinline__ uint32_t smem_u32(const void* p) {
    uint32_t a;
    asm("{ .reg .u64 t; cvta.to.shared.u64 t, %1; cvt.u32.u64 %0, t; }" : "=r"(a) : "l"(p));
    return a;
}
__device__ __forceinline__ void ldsm4(uint32_t* r, uint32_t addr) {
    asm volatile("ldmatrix.sync.aligned.m8n8.x4.shared.b16 {%0,%1,%2,%3}, [%4];"
                 : "=r"(r[0]), "=r"(r[1]), "=r"(r[2]), "=r"(r[3]) : "r"(addr));
}
__device__ __forceinline__ void mma_bf16(float* d, const uint32_t* a,
                                         uint32_t b0, uint32_t b1) {
    asm volatile("mma.sync.aligned.m16n8k16.row.col.f32.bf16.bf16.f32 "
                 "{%0,%1,%2,%3}, {%4,%5,%6,%7}, {%8,%9}, {%0,%1,%2,%3};"
                 : "+f"(d[0]), "+f"(d[1]), "+f"(d[2]), "+f"(d[3])
                 : "r"(a[0]), "r"(a[1]), "r"(a[2]), "r"(a[3]), "r"(b0), "r"(b1));
}
__device__ __forceinline__ uint32_t pack_bf16x2(float x, float y) {
    __nv_bfloat16 hx = __float2bfloat16(x), hy = __float2bfloat16(y);
    return ((uint32_t)__bfloat16_as_ushort(hy) << 16) | (uint32_t)__bfloat16_as_ushort(hx);
}
__device__ __forceinline__ void cp16(uint32_t dst, const void* src) {
    asm volatile("cp.async.cg.shared.global [%0], [%1], 16;" :: "r"(dst), "l"(src));
}
__device__ __forceinline__ float ex2(float x) {
    float r;
    asm("ex2.approx.f32 %0, %1;" : "=f"(r) : "f"(x));
    return r;
}
#define CP_COMMIT() asm volatile("cp.async.commit_group;" ::: "memory")
#define CP_WAIT1()  asm volatile("cp.async.wait_group 1;" ::: "memory")

// ---------------- fused fp32 -> bf16 hi/lo split of x, W_in, W_x --------------
__global__ void split3_kernel(const float* __restrict__ x,
                              const float* __restrict__ W_in,
                              const float* __restrict__ W_x)
{
    const int N1 = MTOK*DMODEL/4, N2 = DINNER*DMODEL/4, N3 = NDBC*DINNER/4;
    int i = blockIdx.x * blockDim.x + threadIdx.x;
    const float* src; __nv_bfloat16 *hi, *lo; int idx;
    if (i < N1)            { src = x;    hi = g_xh;  lo = g_xl;  idx = i; }
    else if (i < N1 + N2)  { src = W_in; hi = g_wih; lo = g_wil; idx = i - N1; }
    else if (i < N1+N2+N3) { src = W_x;  hi = g_wxh; lo = g_wxl; idx = i - N1 - N2; }
    else return;

    float4 v = reinterpret_cast<const float4*>(src)[idx];
    float hx = __bfloat162float(__float2bfloat16(v.x));
    float hy = __bfloat162float(__float2bfloat16(v.y));
    float hz = __bfloat162float(__float2bfloat16(v.z));
    float hw = __bfloat162float(__float2bfloat16(v.w));
    reinterpret_cast<uint2*>(hi)[idx] =
        make_uint2(pack_bf16x2(v.x, v.y), pack_bf16x2(v.z, v.w));
    reinterpret_cast<uint2*>(lo)[idx] =
        make_uint2(pack_bf16x2(v.x - hx, v.y - hy), pack_bf16x2(v.z - hz, v.w - hw));
}

// ====== pipelined bf16 split GEMM, 2-stage cp.async, block 128x64 =============
template<int BN, int EPI>
__global__ __launch_bounds__(256)
void gemm_bs(const __nv_bfloat16* __restrict__ Ah, const __nv_bfloat16* __restrict__ Al,
             const __nv_bfloat16* __restrict__ Bh, const __nv_bfloat16* __restrict__ Bl,
             float* __restrict__ C0, float* __restrict__ C1,
             float* __restrict__ C2, float* __restrict__ C3,
             int kspan, int lda, int ldb, int ldc,
             const float* __restrict__ xsrc, const float* __restrict__ winsrc,
             const float* __restrict__ conv_w, const float* __restrict__ conv_b)
{
    constexpr int BM = 128, BK = 32;
    constexpr int WN = BN / 2;
    constexpr int NT = WN / 8;
    constexpr int PITCH = BK + 8;
    constexpr int OFF_AH = 0;
    constexpr int OFF_AL = BM*PITCH;
    constexpr int OFF_BH = 2*BM*PITCH;
    constexpr int OFF_BL = 2*BM*PITCH + BN*PITCH;
    constexpr int STAGE  = 2*BM*PITCH + 2*BN*PITCH;

    extern __shared__ __align__(16) uint16_t smem[];
    const uint32_t sbase = smem_u32(smem);

    const int tid  = threadIdx.x;
    const int wid  = tid >> 5;
    const int lane = tid & 31;
    const int warp_m = wid & 3;
    const int warp_n = wid >> 2;
    const int m0 = blockIdx.y * BM;
    const int n0 = blockIdx.x * BN;
    const int kbeg = blockIdx.z * kspan;
    const int kend = kbeg + kspan;
    float* C = (blockIdx.z == 0) ? C0 : (blockIdx.z == 1) ? C1
             : (blockIdx.z == 2) ? C2 : C3;

    const int ld_r = tid >> 2;
    const int ld_c = (tid & 3) << 3;

    float acc[2][NT][4];
    #pragma unroll
    for (int mt = 0; mt < 2; ++mt)
        #pragma unroll
        for (int nt = 0; nt < NT; ++nt)
            #pragma unroll
            for (int j = 0; j < 4; ++j) acc[mt][nt][j] = 0.f;

    const int a_row = (lane & 15);
    const int a_koff = (lane >> 4) << 3;
    const int b_row = ((lane >> 4) << 3) + (lane & 7);
    const int b_koff = ((lane >> 3) & 1) << 3;

    auto load_stage = [&](int s, int k0) {
        uint32_t base = sbase + (uint32_t)(s*STAGE*2);
        #pragma unroll
        for (int i = 0; i < 2; ++i) {
            int r = ld_r + i*64;
            uint32_t so = base + (uint32_t)((r*PITCH + ld_c)*2);
            cp16(so + OFF_AH*2, Ah + (size_t)(m0+r)*lda + k0 + ld_c);
            cp16(so + OFF_AL*2, Al + (size_t)(m0+r)*lda + k0 + ld_c);
            if (i*64 < BN) {
                cp16(so + OFF_BH*2, Bh + (size_t)(n0+r)*ldb + k0 + ld_c);
                cp16(so + OFF_BL*2, Bl + (size_t)(n0+r)*ldb + k0 + ld_c);
            }
        }
    };

    load_stage(0, kbeg);
    CP_COMMIT();

    int buf = 0;
    for (int k0 = kbeg; k0 < kend; k0 += BK) {
        if (k0 + BK < kend) load_stage(buf ^ 1, k0 + BK);
        CP_COMMIT();
        CP_WAIT1();
        __syncthreads();

        const uint32_t stg = sbase + (uint32_t)(buf*STAGE*2);
        #pragma unroll
        for (int kstep = 0; kstep < 2; ++kstep) {
            uint32_t aH[2][4], aL[2][4];
            #pragma unroll
            for (int mt = 0; mt < 2; ++mt) {
                uint32_t off = (uint32_t)(((warp_m*32 + mt*16 + a_row)*PITCH
                                          + kstep*16 + a_koff) * 2);
                ldsm4(aH[mt], stg + OFF_AH*2 + off);
                ldsm4(aL[mt], stg + OFF_AL*2 + off);
            }
            #pragma unroll
            for (int p = 0; p < NT/2; ++p) {
                uint32_t off = (uint32_t)(((warp_n*WN + p*16 + b_row)*PITCH
                                          + kstep*16 + b_koff) * 2);
                uint32_t rH[4], rL[4];
                ldsm4(rH, stg + OFF_BH*2 + off);
                ldsm4(rL, stg + OFF_BL*2 + off);
                #pragma unroll
                for (int mt = 0; mt < 2; ++mt) {
                    mma_bf16(acc[mt][2*p],   aH[mt], rH[0], rH[1]);
                    mma_bf16(acc[mt][2*p],   aH[mt], rL[0], rL[1]);
                    mma_bf16(acc[mt][2*p],   aL[mt], rH[0], rH[1]);
                    mma_bf16(acc[mt][2*p+1], aH[mt], rH[2], rH[3]);
                    mma_bf16(acc[mt][2*p+1], aH[mt], rL[2], rL[3]);
                    mma_bf16(acc[mt][2*p+1], aL[mt], rH[2], rH[3]);
                }
            }
        }
        __syncthreads();
        buf ^= 1;
    }

    if (EPI == 0) {
        #pragma unroll
        for (int mt = 0; mt < 2; ++mt) {
            int r0 = m0 + warp_m*32 + mt*16 + (lane >> 2);
            #pragma unroll
            for (int nt = 0; nt < NT; ++nt) {
                int c0 = n0 + warp_n*WN + nt*8 + ((lane & 3) << 1);
                *reinterpret_cast<float2*>(C + (size_t)r0*ldc + c0) =
                    make_float2(acc[mt][nt][0], acc[mt][nt][1]);
                *reinterpret_cast<float2*>(C + (size_t)(r0+8)*ldc + c0) =
                    make_float2(acc[mt][nt][2], acc[mt][nt][3]);
            }
        }
    } else {
        // ===== fused conv + silu epilogue (BN==64 path) =====
        float* sf = reinterpret_cast<float*>(smem);
        #pragma unroll
        for (int mt = 0; mt < 2; ++mt) {
            int r0 = warp_m*32 + mt*16 + (lane >> 2);
            #pragma unroll
            for (int nt = 0; nt < NT; ++nt) {
                int c0 = warp_n*WN + nt*8 + ((lane & 3) << 1);
                *reinterpret_cast<float2*>(sf + (3+r0)*66 + c0) =
                    make_float2(acc[mt][nt][0], acc[mt][nt][1]);
                *reinterpret_cast<float2*>(sf + (11+r0)*66 + c0) =
                    make_float2(acc[mt][nt][2], acc[mt][nt][3]);
            }
        }
        if (tid < 192) {
            int r = tid / 64, c = tid - (tid/64)*64;
            float v = 0.f;
            if ((m0 & (SEQ-1)) != 0) {
                const float* xr = xsrc + (size_t)(m0 - 3 + r)*DMODEL;
                const float* wr = winsrc + (size_t)(n0 + c)*DMODEL;
                float a0 = 0.f, a1 = 0.f, a2 = 0.f, a3 = 0.f;
                #pragma unroll 4
                for (int k = 0; k < DMODEL; k += 4) {
                    float4 xv = *reinterpret_cast<const float4*>(xr + k);
                    float4 wv = *reinterpret_cast<const float4*>(wr + k);
                    a0 = fmaf(xv.x, wv.x, a0);
                    a1 = fmaf(xv.y, wv.y, a1);
                    a2 = fmaf(xv.z, wv.z, a2);
                    a3 = fmaf(xv.w, wv.w, a3);
                }
                v = (a0 + a1) + (a2 + a3);
            }
            sf[r*66 + c] = v;
        }
        __syncthreads();

        const int cpair = tid & 31;
        const int tg = tid >> 5;
        const int c = cpair << 1;
        const float4 w0 = reinterpret_cast<const float4*>(conv_w)[n0 + c];
        const float4 w1 = reinterpret_cast<const float4*>(conv_w)[n0 + c + 1];
        const float b0 = conv_b[n0 + c], b1 = conv_b[n0 + c + 1];
        const int t0 = tg << 4;

        float2 p0 = *reinterpret_cast<float2*>(sf + (t0+0)*66 + c);
        float2 p1 = *reinterpret_cast<float2*>(sf + (t0+1)*66 + c);
        float2 p2 = *reinterpret_cast<float2*>(sf + (t0+2)*66 + c);
        #pragma unroll 4
        for (int i = 0; i < 16; ++i) {
            float2 p3 = *reinterpret_cast<float2*>(sf + (t0+3+i)*66 + c);
            float a0 = b0 + w0.x*p0.x + w0.y*p1.x + w0.z*p2.x + w0.w*p3.x;
            float a1 = b1 + w1.x*p0.y + w1.y*p1.y + w1.z*p2.y + w1.w*p3.y;
            a0 = a0 / (1.f + __expf(-a0));
            a1 = a1 / (1.f + __expf(-a1));
            float h0 = __bfloat162float(__float2bfloat16(a0));
            float h1 = __bfloat162float(__float2bfloat16(a1));
            size_t o = (size_t)(m0 + t0 + i)*DINNER + n0 + c;
            *reinterpret_cast<uint32_t*>(g_xch + o) = pack_bf16x2(a0, a1);
            *reinterpret_cast<uint32_t*>(g_xcl + o) = pack_bf16x2(a0 - h0, a1 - h1);
            p0 = p1; p1 = p2; p2 = p3;
        }
    }
}

// ---------------- selective scan (suffix-sum closed form, no recurrence) ------
// h_T[d,s] = sum_t ex2(A2_s * R_t) * (dt*u)_t * B_t[s],  R_t = sum_{t'>t} dt_t'
// Tiles processed in reverse; only carried dependence is the scalar R_run FADD.
__global__ __launch_bounds__(256)
void scan_kernel(const float* __restrict__ A_log,
                 const float* __restrict__ Dv,
                 const float* __restrict__ W_dt,
                 const float* __restrict__ b_dt,
                 const float* __restrict__ x,
                 const float* __restrict__ W_in)
{
    const int b     = blockIdx.x >> 6;
    const int dbase = (blockIdx.x & 63) << 4;
    const int tid = threadIdx.x;
    const int dl  = tid >> 4;    // 0..15 local channel
    const int s   = tid & 15;    // state
    const int d   = dbase + dl;

    __shared__ float s_wdt[16][33];
    __shared__ float s_bdt[16];
    __shared__ float s_z[16];
    __shared__ float s_r  [64][32];
    __shared__ float s_dtT[16][68];
    __shared__ float s_duT[16][68];
    __shared__ float s_BT [16][68];

    #pragma unroll
    for (int e = tid; e < 16*32; e += 256) {
        int c = e >> 5, r = e & 31;
        s_wdt[c][r] = W_dt[(dbase + c)*DTRANK + r];
    }
    if (tid < 16) s_bdt[tid] = b_dt[dbase + tid];

    // fused zlast: z[dl] = x[b, -1, :] . W_in[1024 + dbase + dl, :]
    {
        const float* xr = x + ((size_t)b*SEQ + (SEQ-1))*DMODEL + s*32;
        const float* wr = W_in + (size_t)(DINNER + dbase + dl)*DMODEL + s*32;
        float a0 = 0.f, a1 = 0.f, a2 = 0.f, a3 = 0.f;
        #pragma unroll
        for (int k = 0; k < 32; k += 4) {
            float4 xv = *reinterpret_cast<const float4*>(xr + k);
            float4 wv = *reinterpret_cast<const float4*>(wr + k);
            a0 = fmaf(xv.x, wv.x, a0);
            a1 = fmaf(xv.y, wv.y, a1);
            a2 = fmaf(xv.z, wv.z, a2);
            a3 = fmaf(xv.w, wv.w, a3);
        }
        float acc = (a0 + a1) + (a2 + a3);
        #pragma unroll
        for (int off = 8; off; off >>= 1)
            acc += __shfl_down_sync(0xffffffffu, acc, off, 16);
        if (s == 0) s_z[dl] = acc;
    }

    const float A2_s = -__expf(A_log[d*DSTATE + s]) * 1.44269504f;
    float R_run = 0.f;
    float acc0 = 0.f, acc1 = 0.f, acc2 = 0.f, acc3 = 0.f;

    // reverse tile order: suffix sums of dt accumulate naturally
    for (int t0 = SEQ - 64; t0 >= 0; t0 -= 64) {
        __syncthreads();
        #pragma unroll
        for (int i = 0; i < 8; ++i) {
            int idx = tid + i*256;
            int tt = idx >> 5, r = idx & 31;
            int g = (b*SEQ + t0 + tt)*NDBC + r;
            s_r[tt][r] = (g_dbcp[0][g] + g_dbcp[1][g])
                       + (g_dbcp[2][g] + g_dbcp[3][g]);
        }
        #pragma unroll
        for (int i = 0; i < 4; ++i) {
            int idx = tid + i*256;
            int tt = idx >> 4, c = idx & 15;
            int m = b*SEQ + t0 + tt;
            size_t o = (size_t)m*DINNER + dbase + c;
            s_duT[c][tt] = __bfloat162float(g_xch[o]) + __bfloat162float(g_xcl[o]);
            int g = m*NDBC + DTRANK + c;
            s_BT[c][tt] = (g_dbcp[0][g] + g_dbcp[1][g])
                        + (g_dbcp[2][g] + g_dbcp[3][g]);
        }
        __syncthreads();
        // dt projection + softplus; du = dt*u
        #pragma unroll
        for (int i = 0; i < 4; ++i) {
            int idx = tid + i*256;
            int tt = idx >> 4, c = idx & 15;
            float acc = s_bdt[c];
            #pragma unroll
            for (int r = 0; r < 32; ++r)
                acc = fmaf(s_r[tt][r], s_wdt[c][r], acc);
            float dt = (acc > 15.f) ? acc : __logf(1.f + __expf(acc));
            s_dtT[c][tt] = dt;
            s_duT[c][tt] *= dt;
        }
        __syncthreads();
        // reverse walk inside the tile, 4 tokens per LDS.128
        #pragma unroll
        for (int t4 = 15; t4 >= 0; --t4) {
            float4 dt4 = *reinterpret_cast<float4*>(&s_dtT[dl][t4*4]);
            float4 du4 = *reinterpret_cast<float4*>(&s_duT[dl][t4*4]);
            float4 B4  = *reinterpret_cast<float4*>(&s_BT [s][t4*4]);
            float Rw = R_run;
            float Rz = Rw + dt4.w;
            float Ry = Rz + dt4.z;
            float Rx = Ry + dt4.y;
            R_run = Rx + dt4.x;
            acc0 = fmaf(ex2(A2_s * Rx), du4.x * B4.x, acc0);
            acc1 = fmaf(ex2(A2_s * Ry), du4.y * B4.y, acc1);
            acc2 = fmaf(ex2(A2_s * Rz), du4.z * B4.z, acc2);
            acc3 = fmaf(ex2(A2_s * Rw), du4.w * B4.w, acc3);
        }
    }

    float h = (acc0 + acc1) + (acc2 + acc3);

    const int mlast = b*SEQ + (SEQ-1);
    int gc = mlast*NDBC + DTRANK + DSTATE + s;
    float Cv = (g_dbcp[0][gc] + g_dbcp[1][gc]) + (g_dbcp[2][gc] + g_dbcp[3][gc]);
    float y = h * Cv;
    #pragma unroll
    for (int off = 8; off; off >>= 1) y += __shfl_down_sync(0xffffffffu, y, off, 16);
    if (s == 0) {
        size_t o = (size_t)mlast*DINNER + d;
        float ul = __bfloat162float(g_xch[o]) + __bfloat162float(g_xcl[o]);
        float zl = s_z[dl];
        float silu_z = zl / (1.f + __expf(-zl));
        g_ylast[b*DINNER + d] = (y + Dv[d]*ul) * silu_z;
    }
}

// ---------------- out projection: last = ylast @ W_out^T ----------------------
__global__ __launch_bounds__(256)
void outproj_kernel(const float* __restrict__ W_out)
{
    const int j = blockIdx.x;
    __shared__ float w[DINNER];
    for (int i = threadIdx.x; i < DINNER; i += 256)
        w[i] = W_out[(size_t)j*DINNER + i];
    __syncthreads();
    const int b = threadIdx.x >> 5;
    const int lane = threadIdx.x & 31;
    float acc = 0.f;
    #pragma unroll 8
    for (int k = lane; k < DINNER; k += 32)
        acc = fmaf(g_ylast[b*DINNER + k], w[k], acc);
    #pragma unroll
    for (int off = 16; off; off >>= 1) acc += __shfl_down_sync(0xffffffffu, acc, off);
    if (lane == 0) g_last[b*DMODEL + j] = acc;
}

// ---------------- layernorm ----------------------------------------------------
__global__ void ln_kernel(const float* __restrict__ ln_g,
                          const float* __restrict__ ln_b)
{
    const int b = blockIdx.x;
    const int j = threadIdx.x;
    __shared__ float rbuf[DMODEL];
    float v = g_last[b*DMODEL + j];
    rbuf[j] = v;
    __syncthreads();
    #pragma unroll
    for (int st = 256; st > 0; st >>= 1) {
        if (j < st) rbuf[j] += rbuf[j + st];
        __syncthreads();
    }
    float mu = rbuf[0] / (float)DMODEL;
    __syncthreads();
    float diff = v - mu;
    rbuf[j] = diff * diff;
    __syncthreads();
    #pragma unroll
    for (int st = 256; st > 0; st >>= 1) {
        if (j < st) rbuf[j] += rbuf[j + st];
        __syncthreads();
    }
    float rstd = rsqrtf(rbuf[0] / (float)DMODEL + 1e-5f);
    g_lastn[b*DMODEL + j] = diff * rstd * ln_g[j] + ln_b[j];
}

// ---------------- head: out = lastn @ head_W^T + head_b ------------------------
__global__ __launch_bounds__(256)
void head_kernel(const float* __restrict__ head_W,
                 const float* __restrict__ head_b,
                 float* __restrict__ out)
{
    const int j = blockIdx.x;
    __shared__ float w[DMODEL];
    for (int i = threadIdx.x; i < DMODEL; i += 256)
        w[i] = head_W[(size_t)j*DMODEL + i];
    __syncthreads();
    const int b = threadIdx.x >> 5;
    const int lane = threadIdx.x & 31;
    float acc = 0.f;
    #pragma unroll 4
    for (int k = lane; k < DMODEL; k += 32)
        acc = fmaf(g_lastn[b*DMODEL + k], w[k], acc);
    #pragma unroll
    for (int off = 16; off; off >>= 1) acc += __shfl_down_sync(0xffffffffu, acc, off);
    if (lane == 0) out[b*DMODEL + j] = acc + head_b[j];
}

// ---------------- launch --------------------------------------------------------
extern "C" void kernel_launch(void* const* d_in, const int* in_sizes, int n_in,
                              void* d_out, int out_size)
{
    const float* x      = (const float*)d_in[0];
    const float* W_in   = (const float*)d_in[1];
    const float* conv_w = (const float*)d_in[2];
    const float* conv_b = (const float*)d_in[3];
    const float* W_x    = (const float*)d_in[4];
    const float* W_dt   = (const float*)d_in[5];
    const float* b_dt   = (const float*)d_in[6];
    const float* A_log  = (const float*)d_in[7];
    const float* Dv     = (const float*)d_in[8];
    const float* W_out  = (const float*)d_in[9];
    const float* ln_g   = (const float*)d_in[10];
    const float* ln_b   = (const float*)d_in[11];
    const float* head_W = (const float*)d_in[12];
    const float* head_b = (const float*)d_in[13];
    float* out = (float*)d_out;

    float *dbcp0, *dbcp1, *dbcp2, *dbcp3;
    cudaGetSymbolAddress((void**)&dbcp0, g_dbcp);
    dbcp1 = dbcp0 + MTOK*NDBC;
    dbcp2 = dbcp1 + MTOK*NDBC;
    dbcp3 = dbcp2 + MTOK*NDBC;
    __nv_bfloat16 *xh, *xl, *wih, *wil, *wxh, *wxl, *xch, *xcl;
    cudaGetSymbolAddress((void**)&xh,  g_xh);
    cudaGetSymbolAddress((void**)&xl,  g_xl);
    cudaGetSymbolAddress((void**)&wih, g_wih);
    cudaGetSymbolAddress((void**)&wil, g_wil);
    cudaGetSymbolAddress((void**)&wxh, g_wxh);
    cudaGetSymbolAddress((void**)&wxl, g_wxl);
    cudaGetSymbolAddress((void**)&xch, g_xch);
    cudaGetSymbolAddress((void**)&xcl, g_xcl);

    const int SMEM2 = (2*128*40 + 2*64*40) * 2 * 2;   // 61440
    cudaFuncSetAttribute((const void*)gemm_bs<64,0>,
                         cudaFuncAttributeMaxDynamicSharedMemorySize, SMEM2);
    cudaFuncSetAttribute((const void*)gemm_bs<64,1>,
                         cudaFuncAttributeMaxDynamicSharedMemorySize, SMEM2);

    // #0: split x, W_in[:1024], W_x into bf16 hi/lo
    {
        const int NT4 = MTOK*DMODEL/4 + DINNER*DMODEL/4 + NDBC*DINNER/4;
        split3_kernel<<<(NT4 + 255)/256, 256>>>(x, W_in, W_x);
    }

    // #1: K1 + fused conv/silu -> xch/xcl
    gemm_bs<64,1><<<dim3(DINNER/64, MTOK/128, 1), 256, SMEM2>>>(
        xh, xl, wih, wil, nullptr, nullptr, nullptr, nullptr,
        DMODEL, DMODEL, DMODEL, 0, x, W_in, conv_w, conv_b);

    // #2: K3: dbc partials = xc @ W_x.T, K split x4
    gemm_bs<64,0><<<dim3(1, MTOK/128, 4), 256, SMEM2>>>(
        xch, xcl, wxh, wxl, dbcp0, dbcp1, dbcp2, dbcp3,
        DINNER/4, DINNER, DINNER, NDBC, nullptr, nullptr, nullptr, nullptr);

    // #3 (ncu target): selective scan — closed-form suffix-sum version
    scan_kernel<<<BATCH * (DINNER/16), 256>>>(A_log, Dv, W_dt, b_dt, x, W_in);

    // #4-#6: out projection, layernorm, head
    outproj_kernel<<<DMODEL, 256>>>(W_out);
    ln_kernel<<<BATCH, DMODEL>>>(ln_g, ln_b);
    head_kernel<<<DMODEL, 256>>>(head_W, head_b, out);
}

// round 14
// speedup vs baseline: 1.0696x; 1.0696x over previous
#include <cuda_runtime.h>
#include <cuda_bf16.h>
#include <cstdint>

#define BATCH   8
#define SEQ     1024
#define DMODEL  512
#define DINNER  1024
#define DSTATE  16
#define DTRANK  32
#define DCONV   4
#define MTOK    (BATCH*SEQ)
#define NDBC    (DTRANK + 2*DSTATE)

// ---------------- scratch -----------------------------------------------------
__device__ float g_dbcp[4][MTOK * NDBC];
__device__ float g_dt [MTOK * DINNER];
__device__ float g_du [MTOK * DINNER];
__device__ float g_ylast[BATCH * DINNER];
__device__ float g_last [BATCH * DMODEL];
__device__ float g_lastn[BATCH * DMODEL];
__device__ __nv_bfloat16 g_xh [MTOK * DMODEL];
__device__ __nv_bfloat16 g_xl [MTOK * DMODEL];
__device__ __nv_bfloat16 g_wih[DINNER * DMODEL];
__device__ __nv_bfloat16 g_wil[DINNER * DMODEL];
__device__ __nv_bfloat16 g_wxh[NDBC * DINNER];
__device__ __nv_bfloat16 g_wxl[NDBC * DINNER];
__device__ __nv_bfloat16 g_xch[MTOK * DINNER];
__device__ __nv_bfloat16 g_xcl[MTOK * DINNER];

// ======================= helpers ==============================================
__device__ __forceinline__ uint32_t smem_u32(const void* p) {
    uint32_t a;
    asm("{ .reg .u64 t; cvta.to.shared.u64 t, %1; cvt.u32.u64 %0, t; }" : "=r"(a) : "l"(p));
    return a;
}
__device__ __forceinline__ void ldsm4(uint32_t* r, uint32_t addr) {
    asm volatile("ldmatrix.sync.aligned.m8n8.x4.shared.b16 {%0,%1,%2,%3}, [%4];"
                 : "=r"(r[0]), "=r"(r[1]), "=r"(r[2]), "=r"(r[3]) : "r"(addr));
}
__device__ __forceinline__ void mma_bf16(float* d, const uint32_t* a,
                                         uint32_t b0, uint32_t b1) {
    asm volatile("mma.sync.aligned.m16n8k16.row.col.f32.bf16.bf16.f32 "
                 "{%0,%1,%2,%3}, {%4,%5,%6,%7}, {%8,%9}, {%0,%1,%2,%3};"
                 : "+f"(d[0]), "+f"(d[1]), "+f"(d[2]), "+f"(d[3])
                 : "r"(a[0]), "r"(a[1]), "r"(a[2]), "r"(a[3]), "r"(b0), "r"(b1));
}
__device__ __forceinline__ uint32_t pack_bf16x2(float x, float y) {
    __nv_bfloat16 hx = __float2bfloat16(x), hy = __float2bfloat16(y);
    return ((uint32_t)__bfloat16_as_ushort(hy) << 16) | (uint32_t)__bfloat16_as_ushort(hx);
}
__device__ __forceinline__ void cp16(uint32_t dst, const void* src) {
    asm volatile("cp.async.cg.shared.global [%0], [%1], 16;" :: "r"(dst), "l"(src));
}
__device__ __forceinline__ float ex2(float x) {
    float r;
    asm("ex2.approx.f32 %0, %1;" : "=f"(r) : "f"(x));
    return r;
}
#define CP_COMMIT() asm volatile("cp.async.commit_group;" ::: "memory")
#define CP_WAIT1()  asm volatile("cp.async.wait_group 1;" ::: "memory")

// ---------------- fused fp32 -> bf16 hi/lo split of x, W_in, W_x --------------
__global__ void split3_kernel(const float* __restrict__ x,
                              const float* __restrict__ W_in,
                              const float* __restrict__ W_x)
{
    const int N1 = MTOK*DMODEL/4, N2 = DINNER*DMODEL/4, N3 = NDBC*DINNER/4;
    int i = blockIdx.x * blockDim.x + threadIdx.x;
    const float* src; __nv_bfloat16 *hi, *lo; int idx;
    if (i < N1)            { src = x;    hi = g_xh;  lo = g_xl;  idx = i; }
    else if (i < N1 + N2)  { src = W_in; hi = g_wih; lo = g_wil; idx = i - N1; }
    else if (i < N1+N2+N3) { src = W_x;  hi = g_wxh; lo = g_wxl; idx = i - N1 - N2; }
    else return;

    float4 v = reinterpret_cast<const float4*>(src)[idx];
    float hx = __bfloat162float(__float2bfloat16(v.x));
    float hy = __bfloat162float(__float2bfloat16(v.y));
    float hz = __bfloat162float(__float2bfloat16(v.z));
    float hw = __bfloat162float(__float2bfloat16(v.w));
    reinterpret_cast<uint2*>(hi)[idx] =
        make_uint2(pack_bf16x2(v.x, v.y), pack_bf16x2(v.z, v.w));
    reinterpret_cast<uint2*>(lo)[idx] =
        make_uint2(pack_bf16x2(v.x - hx, v.y - hy), pack_bf16x2(v.z - hz, v.w - hw));
}

// ====== pipelined bf16 split GEMM, 2-stage cp.async, block 128x64 =============
template<int BN, int EPI>
__global__ __launch_bounds__(256)
void gemm_bs(const __nv_bfloat16* __restrict__ Ah, const __nv_bfloat16* __restrict__ Al,
             const __nv_bfloat16* __restrict__ Bh, const __nv_bfloat16* __restrict__ Bl,
             float* __restrict__ C0, float* __restrict__ C1,
             float* __restrict__ C2, float* __restrict__ C3,
             int kspan, int lda, int ldb, int ldc,
             const float* __restrict__ xsrc, const float* __restrict__ winsrc,
             const float* __restrict__ conv_w, const float* __restrict__ conv_b)
{
    constexpr int BM = 128, BK = 32;
    constexpr int WN = BN / 2;
    constexpr int NT = WN / 8;
    constexpr int PITCH = BK + 8;
    constexpr int OFF_AH = 0;
    constexpr int OFF_AL = BM*PITCH;
    constexpr int OFF_BH = 2*BM*PITCH;
    constexpr int OFF_BL = 2*BM*PITCH + BN*PITCH;
    constexpr int STAGE  = 2*BM*PITCH + 2*BN*PITCH;

    extern __shared__ __align__(16) uint16_t smem[];
    const uint32_t sbase = smem_u32(smem);

    const int tid  = threadIdx.x;
    const int wid  = tid >> 5;
    const int lane = tid & 31;
    const int warp_m = wid & 3;
    const int warp_n = wid >> 2;
    const int m0 = blockIdx.y * BM;
    const int n0 = blockIdx.x * BN;
    const int kbeg = blockIdx.z * kspan;
    const int kend = kbeg + kspan;
    float* C = (blockIdx.z == 0) ? C0 : (blockIdx.z == 1) ? C1
             : (blockIdx.z == 2) ? C2 : C3;

    const int ld_r = tid >> 2;
    const int ld_c = (tid & 3) << 3;

    float acc[2][NT][4];
    #pragma unroll
    for (int mt = 0; mt < 2; ++mt)
        #pragma unroll
        for (int nt = 0; nt < NT; ++nt)
            #pragma unroll
            for (int j = 0; j < 4; ++j) acc[mt][nt][j] = 0.f;

    const int a_row = (lane & 15);
    const int a_koff = (lane >> 4) << 3;
    const int b_row = ((lane >> 4) << 3) + (lane & 7);
    const int b_koff = ((lane >> 3) & 1) << 3;

    auto load_stage = [&](int s, int k0) {
        uint32_t base = sbase + (uint32_t)(s*STAGE*2);
        #pragma unroll
        for (int i = 0; i < 2; ++i) {
            int r = ld_r + i*64;
            uint32_t so = base + (uint32_t)((r*PITCH + ld_c)*2);
            cp16(so + OFF_AH*2, Ah + (size_t)(m0+r)*lda + k0 + ld_c);
            cp16(so + OFF_AL*2, Al + (size_t)(m0+r)*lda + k0 + ld_c);
            if (i*64 < BN) {
                cp16(so + OFF_BH*2, Bh + (size_t)(n0+r)*ldb + k0 + ld_c);
                cp16(so + OFF_BL*2, Bl + (size_t)(n0+r)*ldb + k0 + ld_c);
            }
        }
    };

    load_stage(0, kbeg);
    CP_COMMIT();

    int buf = 0;
    for (int k0 = kbeg; k0 < kend; k0 += BK) {
        if (k0 + BK < kend) load_stage(buf ^ 1, k0 + BK);
        CP_COMMIT();
        CP_WAIT1();
        __syncthreads();

        const uint32_t stg = sbase + (uint32_t)(buf*STAGE*2);
        #pragma unroll
        for (int kstep = 0; kstep < 2; ++kstep) {
            uint32_t aH[2][4], aL[2][4];
            #pragma unroll
            for (int mt = 0; mt < 2; ++mt) {
                uint32_t off = (uint32_t)(((warp_m*32 + mt*16 + a_row)*PITCH
                                          + kstep*16 + a_koff) * 2);
                ldsm4(aH[mt], stg + OFF_AH*2 + off);
                ldsm4(aL[mt], stg + OFF_AL*2 + off);
            }
            #pragma unroll
            for (int p = 0; p < NT/2; ++p) {
                uint32_t off = (uint32_t)(((warp_n*WN + p*16 + b_row)*PITCH
                                          + kstep*16 + b_koff) * 2);
                uint32_t rH[4], rL[4];
                ldsm4(rH, stg + OFF_BH*2 + off);
                ldsm4(rL, stg + OFF_BL*2 + off);
                #pragma unroll
                for (int mt = 0; mt < 2; ++mt) {
                    mma_bf16(acc[mt][2*p],   aH[mt], rH[0], rH[1]);
                    mma_bf16(acc[mt][2*p],   aH[mt], rL[0], rL[1]);
                    mma_bf16(acc[mt][2*p],   aL[mt], rH[0], rH[1]);
                    mma_bf16(acc[mt][2*p+1], aH[mt], rH[2], rH[3]);
                    mma_bf16(acc[mt][2*p+1], aH[mt], rL[2], rL[3]);
                    mma_bf16(acc[mt][2*p+1], aL[mt], rH[2], rH[3]);
                }
            }
        }
        __syncthreads();
        buf ^= 1;
    }

    if (EPI == 0) {
        #pragma unroll
        for (int mt = 0; mt < 2; ++mt) {
            int r0 = m0 + warp_m*32 + mt*16 + (lane >> 2);
            #pragma unroll
            for (int nt = 0; nt < NT; ++nt) {
                int c0 = n0 + warp_n*WN + nt*8 + ((lane & 3) << 1);
                *reinterpret_cast<float2*>(C + (size_t)r0*ldc + c0) =
                    make_float2(acc[mt][nt][0], acc[mt][nt][1]);
                *reinterpret_cast<float2*>(C + (size_t)(r0+8)*ldc + c0) =
                    make_float2(acc[mt][nt][2], acc[mt][nt][3]);
            }
        }
    } else {
        // ===== fused conv + silu epilogue (BN==64 path) =====
        float* sf = reinterpret_cast<float*>(smem);
        #pragma unroll
        for (int mt = 0; mt < 2; ++mt) {
            int r0 = warp_m*32 + mt*16 + (lane >> 2);
            #pragma unroll
            for (int nt = 0; nt < NT; ++nt) {
                int c0 = warp_n*WN + nt*8 + ((lane & 3) << 1);
                *reinterpret_cast<float2*>(sf + (3+r0)*66 + c0) =
                    make_float2(acc[mt][nt][0], acc[mt][nt][1]);
                *reinterpret_cast<float2*>(sf + (11+r0)*66 + c0) =
                    make_float2(acc[mt][nt][2], acc[mt][nt][3]);
            }
        }
        if (tid < 192) {
            int r = tid / 64, c = tid - (tid/64)*64;
            float v = 0.f;
            if ((m0 & (SEQ-1)) != 0) {
                const float* xr = xsrc + (size_t)(m0 - 3 + r)*DMODEL;
                const float* wr = winsrc + (size_t)(n0 + c)*DMODEL;
                float a0 = 0.f, a1 = 0.f, a2 = 0.f, a3 = 0.f;
                #pragma unroll 4
                for (int k = 0; k < DMODEL; k += 4) {
                    float4 xv = *reinterpret_cast<const float4*>(xr + k);
                    float4 wv = *reinterpret_cast<const float4*>(wr + k);
                    a0 = fmaf(xv.x, wv.x, a0);
                    a1 = fmaf(xv.y, wv.y, a1);
                    a2 = fmaf(xv.z, wv.z, a2);
                    a3 = fmaf(xv.w, wv.w, a3);
                }
                v = (a0 + a1) + (a2 + a3);
            }
            sf[r*66 + c] = v;
        }
        __syncthreads();

        const int cpair = tid & 31;
        const int tg = tid >> 5;
        const int c = cpair << 1;
        const float4 w0 = reinterpret_cast<const float4*>(conv_w)[n0 + c];
        const float4 w1 = reinterpret_cast<const float4*>(conv_w)[n0 + c + 1];
        const float b0 = conv_b[n0 + c], b1 = conv_b[n0 + c + 1];
        const int t0 = tg << 4;

        float2 p0 = *reinterpret_cast<float2*>(sf + (t0+0)*66 + c);
        float2 p1 = *reinterpret_cast<float2*>(sf + (t0+1)*66 + c);
        float2 p2 = *reinterpret_cast<float2*>(sf + (t0+2)*66 + c);
        #pragma unroll 4
        for (int i = 0; i < 16; ++i) {
            float2 p3 = *reinterpret_cast<float2*>(sf + (t0+3+i)*66 + c);
            float a0 = b0 + w0.x*p0.x + w0.y*p1.x + w0.z*p2.x + w0.w*p3.x;
            float a1 = b1 + w1.x*p0.y + w1.y*p1.y + w1.z*p2.y + w1.w*p3.y;
            a0 = a0 / (1.f + __expf(-a0));
            a1 = a1 / (1.f + __expf(-a1));
            float h0 = __bfloat162float(__float2bfloat16(a0));
            float h1 = __bfloat162float(__float2bfloat16(a1));
            size_t o = (size_t)(m0 + t0 + i)*DINNER + n0 + c;
            *reinterpret_cast<uint32_t*>(g_xch + o) = pack_bf16x2(a0, a1);
            *reinterpret_cast<uint32_t*>(g_xcl + o) = pack_bf16x2(a0 - h0, a1 - h1);
            p0 = p1; p1 = p2; p2 = p3;
        }
    }
}

// ---------------- dt + du: dt = softplus(dbc[:,:32]@W_dt^T + b_dt), du = dt*u --
// NOTE: s_r pitch must be a multiple of 4 floats for the float4 reads (round-13
// crash was pitch 33 -> misaligned LDS.128 on odd rows).
__global__ __launch_bounds__(256)
void dtdu_kernel(const float* __restrict__ W_dt, const float* __restrict__ b_dt)
{
    const int c  = blockIdx.x * 256 + threadIdx.x;   // channel
    const int m0 = blockIdx.y * 32;                  // token group
    const int tid = threadIdx.x;

    float w[DTRANK];
    #pragma unroll
    for (int k = 0; k < DTRANK; k += 4) {
        float4 v = *reinterpret_cast<const float4*>(W_dt + (size_t)c*DTRANK + k);
        w[k] = v.x; w[k+1] = v.y; w[k+2] = v.z; w[k+3] = v.w;
    }
    const float bias = b_dt[c];

    __shared__ __align__(16) float s_r[32][36];   // pitch 36 floats = 144B (16B mult.)
    #pragma unroll
    for (int i = 0; i < 4; ++i) {
        int e = tid + i*256;
        int tt = e >> 5, r = e & 31;
        int g = (m0 + tt)*NDBC + r;
        s_r[tt][r] = (g_dbcp[0][g] + g_dbcp[1][g]) + (g_dbcp[2][g] + g_dbcp[3][g]);
    }
    __syncthreads();

    #pragma unroll 2
    for (int tt = 0; tt < 32; ++tt) {
        float acc = bias;
        #pragma unroll
        for (int k = 0; k < DTRANK; k += 4) {
            float4 r4 = *reinterpret_cast<const float4*>(&s_r[tt][k]);
            acc = fmaf(r4.x, w[k],   acc);
            acc = fmaf(r4.y, w[k+1], acc);
            acc = fmaf(r4.z, w[k+2], acc);
            acc = fmaf(r4.w, w[k+3], acc);
        }
        float dt = (acc > 15.f) ? acc : __logf(1.f + __expf(acc));
        size_t o = (size_t)(m0 + tt)*DINNER + c;
        float u = __bfloat162float(g_xch[o]) + __bfloat162float(g_xcl[o]);
        g_dt[o] = dt;
        g_du[o] = dt * u;
    }
}

// ---------------- selective scan (loads precomputed dt/du; fused zlast) -------
__global__ __launch_bounds__(256)
void scan_kernel(const float* __restrict__ A_log,
                 const float* __restrict__ Dv,
                 const float* __restrict__ x,
                 const float* __restrict__ W_in)
{
    const int b     = blockIdx.x >> 6;
    const int dbase = (blockIdx.x & 63) << 4;
    const int tid = threadIdx.x;
    const int dl  = tid >> 4;    // 0..15 local channel
    const int s   = tid & 15;    // state
    const int d   = dbase + dl;

    __shared__ float s_z[16];
    __shared__ __align__(16) float s_dtT[16][68];
    __shared__ __align__(16) float s_duT[16][68];
    __shared__ __align__(16) float s_BT [16][68];

    // fused zlast: z[dl] = x[b, -1, :] . W_in[1024 + dbase + dl, :]
    {
        const float* xr = x + ((size_t)b*SEQ + (SEQ-1))*DMODEL + s*32;
        const float* wr = W_in + (size_t)(DINNER + dbase + dl)*DMODEL + s*32;
        float a0 = 0.f, a1 = 0.f, a2 = 0.f, a3 = 0.f;
        #pragma unroll
        for (int k = 0; k < 32; k += 4) {
            float4 xv = *reinterpret_cast<const float4*>(xr + k);
            float4 wv = *reinterpret_cast<const float4*>(wr + k);
            a0 = fmaf(xv.x, wv.x, a0);
            a1 = fmaf(xv.y, wv.y, a1);
            a2 = fmaf(xv.z, wv.z, a2);
            a3 = fmaf(xv.w, wv.w, a3);
        }
        float acc = (a0 + a1) + (a2 + a3);
        #pragma unroll
        for (int off = 8; off; off >>= 1)
            acc += __shfl_down_sync(0xffffffffu, acc, off, 16);
        if (s == 0) s_z[dl] = acc;
    }

    const float A2_s = -__expf(A_log[d*DSTATE + s]) * 1.44269504f;
    float h = 0.f;

    for (int t0 = 0; t0 < SEQ; t0 += 64) {
        __syncthreads();
        #pragma unroll
        for (int i = 0; i < 4; ++i) {
            int idx = tid + i*256;
            int tt = idx >> 4, c = idx & 15;
            int m = b*SEQ + t0 + tt;
            size_t o = (size_t)m*DINNER + dbase + c;
            s_dtT[c][tt] = g_dt[o];
            s_duT[c][tt] = g_du[o];
            int g = m*NDBC + DTRANK + c;
            s_BT[c][tt] = (g_dbcp[0][g] + g_dbcp[1][g])
                        + (g_dbcp[2][g] + g_dbcp[3][g]);
        }
        __syncthreads();
        #pragma unroll
        for (int t4 = 0; t4 < 16; ++t4) {
            float4 dt4 = *reinterpret_cast<float4*>(&s_dtT[dl][t4*4]);
            float4 du4 = *reinterpret_cast<float4*>(&s_duT[dl][t4*4]);
            float4 B4  = *reinterpret_cast<float4*>(&s_BT [s][t4*4]);
            h = fmaf(ex2(dt4.x * A2_s), h, du4.x * B4.x);
            h = fmaf(ex2(dt4.y * A2_s), h, du4.y * B4.y);
            h = fmaf(ex2(dt4.z * A2_s), h, du4.z * B4.z);
            h = fmaf(ex2(dt4.w * A2_s), h, du4.w * B4.w);
        }
    }

    const int mlast = b*SEQ + (SEQ-1);
    int gc = mlast*NDBC + DTRANK + DSTATE + s;
    float Cv = (g_dbcp[0][gc] + g_dbcp[1][gc]) + (g_dbcp[2][gc] + g_dbcp[3][gc]);
    float y = h * Cv;
    #pragma unroll
    for (int off = 8; off; off >>= 1) y += __shfl_down_sync(0xffffffffu, y, off, 16);
    if (s == 0) {
        size_t o = (size_t)mlast*DINNER + d;
        float ul = __bfloat162float(g_xch[o]) + __bfloat162float(g_xcl[o]);
        float zl = s_z[dl];
        float silu_z = zl / (1.f + __expf(-zl));
        g_ylast[b*DINNER + d] = (y + Dv[d]*ul) * silu_z;
    }
}

// ---------------- out projection: last = ylast @ W_out^T ----------------------
__global__ __launch_bounds__(256)
void outproj_kernel(const float* __restrict__ W_out)
{
    const int j = blockIdx.x;
    __shared__ float w[DINNER];
    for (int i = threadIdx.x; i < DINNER; i += 256)
        w[i] = W_out[(size_t)j*DINNER + i];
    __syncthreads();
    const int b = threadIdx.x >> 5;
    const int lane = threadIdx.x & 31;
    float acc = 0.f;
    #pragma unroll 8
    for (int k = lane; k < DINNER; k += 32)
        acc = fmaf(g_ylast[b*DINNER + k], w[k], acc);
    #pragma unroll
    for (int off = 16; off; off >>= 1) acc += __shfl_down_sync(0xffffffffu, acc, off);
    if (lane == 0) g_last[b*DMODEL + j] = acc;
}

// ---------------- layernorm ----------------------------------------------------
__global__ void ln_kernel(const float* __restrict__ ln_g,
                          const float* __restrict__ ln_b)
{
    const int b = blockIdx.x;
    const int j = threadIdx.x;
    __shared__ float rbuf[DMODEL];
    float v = g_last[b*DMODEL + j];
    rbuf[j] = v;
    __syncthreads();
    #pragma unroll
    for (int st = 256; st > 0; st >>= 1) {
        if (j < st) rbuf[j] += rbuf[j + st];
        __syncthreads();
    }
    float mu = rbuf[0] / (float)DMODEL;
    __syncthreads();
    float diff = v - mu;
    rbuf[j] = diff * diff;
    __syncthreads();
    #pragma unroll
    for (int st = 256; st > 0; st >>= 1) {
        if (j < st) rbuf[j] += rbuf[j + st];
        __syncthreads();
    }
    float rstd = rsqrtf(rbuf[0] / (float)DMODEL + 1e-5f);
    g_lastn[b*DMODEL + j] = diff * rstd * ln_g[j] + ln_b[j];
}

// ---------------- head: out = lastn @ head_W^T + head_b ------------------------
__global__ __launch_bounds__(256)
void head_kernel(const float* __restrict__ head_W,
                 const float* __restrict__ head_b,
                 float* __restrict__ out)
{
    const int j = blockIdx.x;
    __shared__ float w[DMODEL];
    for (int i = threadIdx.x; i < DMODEL; i += 256)
        w[i] = head_W[(size_t)j*DMODEL + i];
    __syncthreads();
    const int b = threadIdx.x >> 5;
    const int lane = threadIdx.x & 31;
    float acc = 0.f;
    #pragma unroll 4
    for (int k = lane; k < DMODEL; k += 32)
        acc = fmaf(g_lastn[b*DMODEL + k], w[k], acc);
    #pragma unroll
    for (int off = 16; off; off >>= 1) acc += __shfl_down_sync(0xffffffffu, acc, off);
    if (lane == 0) out[b*DMODEL + j] = acc + head_b[j];
}

// ---------------- launch --------------------------------------------------------
extern "C" void kernel_launch(void* const* d_in, const int* in_sizes, int n_in,
                              void* d_out, int out_size)
{
    const float* x      = (const float*)d_in[0];
    const float* W_in   = (const float*)d_in[1];
    const float* conv_w = (const float*)d_in[2];
    const float* conv_b = (const float*)d_in[3];
    const float* W_x    = (const float*)d_in[4];
    const float* W_dt   = (const float*)d_in[5];
    const float* b_dt   = (const float*)d_in[6];
    const float* A_log  = (const float*)d_in[7];
    const float* Dv     = (const float*)d_in[8];
    const float* W_out  = (const float*)d_in[9];
    const float* ln_g   = (const float*)d_in[10];
    const float* ln_b   = (const float*)d_in[11];
    const float* head_W = (const float*)d_in[12];
    const float* head_b = (const float*)d_in[13];
    float* out = (float*)d_out;

    float *dbcp0, *dbcp1, *dbcp2, *dbcp3;
    cudaGetSymbolAddress((void**)&dbcp0, g_dbcp);
    dbcp1 = dbcp0 + MTOK*NDBC;
    dbcp2 = dbcp1 + MTOK*NDBC;
    dbcp3 = dbcp2 + MTOK*NDBC;
    __nv_bfloat16 *xh, *xl, *wih, *wil, *wxh, *wxl, *xch, *xcl;
    cudaGetSymbolAddress((void**)&xh,  g_xh);
    cudaGetSymbolAddress((void**)&xl,  g_xl);
    cudaGetSymbolAddress((void**)&wih, g_wih);
    cudaGetSymbolAddress((void**)&wil, g_wil);
    cudaGetSymbolAddress((void**)&wxh, g_wxh);
    cudaGetSymbolAddress((void**)&wxl, g_wxl);
    cudaGetSymbolAddress((void**)&xch, g_xch);
    cudaGetSymbolAddress((void**)&xcl, g_xcl);

    const int SMEM2 = (2*128*40 + 2*64*40) * 2 * 2;   // 61440
    cudaFuncSetAttribute((const void*)gemm_bs<64,0>,
                         cudaFuncAttributeMaxDynamicSharedMemorySize, SMEM2);
    cudaFuncSetAttribute((const void*)gemm_bs<64,1>,
                         cudaFuncAttributeMaxDynamicSharedMemorySize, SMEM2);

    // #0: split x, W_in[:1024], W_x into bf16 hi/lo
    {
        const int NT4 = MTOK*DMODEL/4 + DINNER*DMODEL/4 + NDBC*DINNER/4;
        split3_kernel<<<(NT4 + 255)/256, 256>>>(x, W_in, W_x);
    }

    // #1: K1 + fused conv/silu -> xch/xcl
    gemm_bs<64,1><<<dim3(DINNER/64, MTOK/128, 1), 256, SMEM2>>>(
        xh, xl, wih, wil, nullptr, nullptr, nullptr, nullptr,
        DMODEL, DMODEL, DMODEL, 0, x, W_in, conv_w, conv_b);

    // #2: K3: dbc partials = xc @ W_x.T, K split x4
    gemm_bs<64,0><<<dim3(1, MTOK/128, 4), 256, SMEM2>>>(
        xch, xcl, wxh, wxl, dbcp0, dbcp1, dbcp2, dbcp3,
        DINNER/4, DINNER, DINNER, NDBC, nullptr, nullptr, nullptr, nullptr);

    // #3 (ncu target): dt + du precompute (evicted from scan)
    dtdu_kernel<<<dim3(DINNER/256, MTOK/32), 256>>>(W_dt, b_dt);

    // #4: selective scan (lean: loads dt/du, fused zlast)
    scan_kernel<<<BATCH * (DINNER/16), 256>>>(A_log, Dv, x, W_in);

    // #5-#7: out projection, layernorm, head
    outproj_kernel<<<DMODEL, 256>>>(W_out);
    ln_kernel<<<BATCH, DMODEL>>>(ln_g, ln_b);
    head_kernel<<<DMODEL, 256>>>(head_W, head_b, out);
}

// round 15
// speedup vs baseline: 1.0717x; 1.0019x over previous
#include <cuda_runtime.h>
#include <cuda_bf16.h>
#include <cstdint>

#define BATCH   8
#define SEQ     1024
#define DMODEL  512
#define DINNER  1024
#define DSTATE  16
#define DTRANK  32
#define DCONV   4
#define MTOK    (BATCH*SEQ)
#define NDBC    (DTRANK + 2*DSTATE)

// ---------------- scratch -----------------------------------------------------
__device__ float g_dbcp[4][MTOK * NDBC];
__device__ float g_dt [MTOK * DINNER];
__device__ float g_du [MTOK * DINNER];
__device__ float g_ylast[BATCH * DINNER];
__device__ float g_last [BATCH * DMODEL];
__device__ float g_lastn[BATCH * DMODEL];
__device__ __nv_bfloat16 g_xh [MTOK * DMODEL];
__device__ __nv_bfloat16 g_xl [MTOK * DMODEL];
__device__ __nv_bfloat16 g_wih[DINNER * DMODEL];
__device__ __nv_bfloat16 g_wil[DINNER * DMODEL];
__device__ __nv_bfloat16 g_wxh[NDBC * DINNER];
__device__ __nv_bfloat16 g_wxl[NDBC * DINNER];
__device__ __nv_bfloat16 g_xch[MTOK * DINNER];
__device__ __nv_bfloat16 g_xcl[MTOK * DINNER];

// ======================= helpers ==============================================
__device__ __forceinline__ uint32_t smem_u32(const void* p) {
    uint32_t a;
    asm("{ .reg .u64 t; cvta.to.shared.u64 t, %1; cvt.u32.u64 %0, t; }" : "=r"(a) : "l"(p));
    return a;
}
__device__ __forceinline__ void ldsm4(uint32_t* r, uint32_t addr) {
    asm volatile("ldmatrix.sync.aligned.m8n8.x4.shared.b16 {%0,%1,%2,%3}, [%4];"
                 : "=r"(r[0]), "=r"(r[1]), "=r"(r[2]), "=r"(r[3]) : "r"(addr));
}
__device__ __forceinline__ void mma_bf16(float* d, const uint32_t* a,
                                         uint32_t b0, uint32_t b1) {
    asm volatile("mma.sync.aligned.m16n8k16.row.col.f32.bf16.bf16.f32 "
                 "{%0,%1,%2,%3}, {%4,%5,%6,%7}, {%8,%9}, {%0,%1,%2,%3};"
                 : "+f"(d[0]), "+f"(d[1]), "+f"(d[2]), "+f"(d[3])
                 : "r"(a[0]), "r"(a[1]), "r"(a[2]), "r"(a[3]), "r"(b0), "r"(b1));
}
__device__ __forceinline__ uint32_t pack_bf16x2(float x, float y) {
    __nv_bfloat16 hx = __float2bfloat16(x), hy = __float2bfloat16(y);
    return ((uint32_t)__bfloat16_as_ushort(hy) << 16) | (uint32_t)__bfloat16_as_ushort(hx);
}
__device__ __forceinline__ void cp16(uint32_t dst, const void* src) {
    asm volatile("cp.async.cg.shared.global [%0], [%1], 16;" :: "r"(dst), "l"(src));
}
__device__ __forceinline__ float ex2(float x) {
    float r;
    asm("ex2.approx.f32 %0, %1;" : "=f"(r) : "f"(x));
    return r;
}
__device__ __forceinline__ float bf2sum(uint32_t hi, uint32_t lo, int half) {
    // unpack bf16x2 words and return hi[half] + lo[half]
    uint16_t h = (half ? (hi >> 16) : hi) & 0xffff;
    uint16_t l = (half ? (lo >> 16) : lo) & 0xffff;
    return __bfloat162float(__ushort_as_bfloat16(h)) +
           __bfloat162float(__ushort_as_bfloat16(l));
}
#define CP_COMMIT() asm volatile("cp.async.commit_group;" ::: "memory")
#define CP_WAIT1()  asm volatile("cp.async.wait_group 1;" ::: "memory")

// ---------------- fused fp32 -> bf16 hi/lo split of x, W_in, W_x --------------
__global__ void split3_kernel(const float* __restrict__ x,
                              const float* __restrict__ W_in,
                              const float* __restrict__ W_x)
{
    const int N1 = MTOK*DMODEL/4, N2 = DINNER*DMODEL/4, N3 = NDBC*DINNER/4;
    int i = blockIdx.x * blockDim.x + threadIdx.x;
    const float* src; __nv_bfloat16 *hi, *lo; int idx;
    if (i < N1)            { src = x;    hi = g_xh;  lo = g_xl;  idx = i; }
    else if (i < N1 + N2)  { src = W_in; hi = g_wih; lo = g_wil; idx = i - N1; }
    else if (i < N1+N2+N3) { src = W_x;  hi = g_wxh; lo = g_wxl; idx = i - N1 - N2; }
    else return;

    float4 v = reinterpret_cast<const float4*>(src)[idx];
    float hx = __bfloat162float(__float2bfloat16(v.x));
    float hy = __bfloat162float(__float2bfloat16(v.y));
    float hz = __bfloat162float(__float2bfloat16(v.z));
    float hw = __bfloat162float(__float2bfloat16(v.w));
    reinterpret_cast<uint2*>(hi)[idx] =
        make_uint2(pack_bf16x2(v.x, v.y), pack_bf16x2(v.z, v.w));
    reinterpret_cast<uint2*>(lo)[idx] =
        make_uint2(pack_bf16x2(v.x - hx, v.y - hy), pack_bf16x2(v.z - hz, v.w - hw));
}

// ====== pipelined bf16 split GEMM, 2-stage cp.async, block 128x64 =============
template<int BN, int EPI>
__global__ __launch_bounds__(256)
void gemm_bs(const __nv_bfloat16* __restrict__ Ah, const __nv_bfloat16* __restrict__ Al,
             const __nv_bfloat16* __restrict__ Bh, const __nv_bfloat16* __restrict__ Bl,
             float* __restrict__ C0, float* __restrict__ C1,
             float* __restrict__ C2, float* __restrict__ C3,
             int kspan, int lda, int ldb, int ldc,
             const float* __restrict__ xsrc, const float* __restrict__ winsrc,
             const float* __restrict__ conv_w, const float* __restrict__ conv_b)
{
    constexpr int BM = 128, BK = 32;
    constexpr int WN = BN / 2;
    constexpr int NT = WN / 8;
    constexpr int PITCH = BK + 8;
    constexpr int OFF_AH = 0;
    constexpr int OFF_AL = BM*PITCH;
    constexpr int OFF_BH = 2*BM*PITCH;
    constexpr int OFF_BL = 2*BM*PITCH + BN*PITCH;
    constexpr int STAGE  = 2*BM*PITCH + 2*BN*PITCH;

    extern __shared__ __align__(16) uint16_t smem[];
    const uint32_t sbase = smem_u32(smem);

    const int tid  = threadIdx.x;
    const int wid  = tid >> 5;
    const int lane = tid & 31;
    const int warp_m = wid & 3;
    const int warp_n = wid >> 2;
    const int m0 = blockIdx.y * BM;
    const int n0 = blockIdx.x * BN;
    const int kbeg = blockIdx.z * kspan;
    const int kend = kbeg + kspan;
    float* C = (blockIdx.z == 0) ? C0 : (blockIdx.z == 1) ? C1
             : (blockIdx.z == 2) ? C2 : C3;

    const int ld_r = tid >> 2;
    const int ld_c = (tid & 3) << 3;

    float acc[2][NT][4];
    #pragma unroll
    for (int mt = 0; mt < 2; ++mt)
        #pragma unroll
        for (int nt = 0; nt < NT; ++nt)
            #pragma unroll
            for (int j = 0; j < 4; ++j) acc[mt][nt][j] = 0.f;

    const int a_row = (lane & 15);
    const int a_koff = (lane >> 4) << 3;
    const int b_row = ((lane >> 4) << 3) + (lane & 7);
    const int b_koff = ((lane >> 3) & 1) << 3;

    auto load_stage = [&](int s, int k0) {
        uint32_t base = sbase + (uint32_t)(s*STAGE*2);
        #pragma unroll
        for (int i = 0; i < 2; ++i) {
            int r = ld_r + i*64;
            uint32_t so = base + (uint32_t)((r*PITCH + ld_c)*2);
            cp16(so + OFF_AH*2, Ah + (size_t)(m0+r)*lda + k0 + ld_c);
            cp16(so + OFF_AL*2, Al + (size_t)(m0+r)*lda + k0 + ld_c);
            if (i*64 < BN) {
                cp16(so + OFF_BH*2, Bh + (size_t)(n0+r)*ldb + k0 + ld_c);
                cp16(so + OFF_BL*2, Bl + (size_t)(n0+r)*ldb + k0 + ld_c);
            }
        }
    };

    load_stage(0, kbeg);
    CP_COMMIT();

    int buf = 0;
    for (int k0 = kbeg; k0 < kend; k0 += BK) {
        if (k0 + BK < kend) load_stage(buf ^ 1, k0 + BK);
        CP_COMMIT();
        CP_WAIT1();
        __syncthreads();

        const uint32_t stg = sbase + (uint32_t)(buf*STAGE*2);
        #pragma unroll
        for (int kstep = 0; kstep < 2; ++kstep) {
            uint32_t aH[2][4], aL[2][4];
            #pragma unroll
            for (int mt = 0; mt < 2; ++mt) {
                uint32_t off = (uint32_t)(((warp_m*32 + mt*16 + a_row)*PITCH
                                          + kstep*16 + a_koff) * 2);
                ldsm4(aH[mt], stg + OFF_AH*2 + off);
                ldsm4(aL[mt], stg + OFF_AL*2 + off);
            }
            #pragma unroll
            for (int p = 0; p < NT/2; ++p) {
                uint32_t off = (uint32_t)(((warp_n*WN + p*16 + b_row)*PITCH
                                          + kstep*16 + b_koff) * 2);
                uint32_t rH[4], rL[4];
                ldsm4(rH, stg + OFF_BH*2 + off);
                ldsm4(rL, stg + OFF_BL*2 + off);
                #pragma unroll
                for (int mt = 0; mt < 2; ++mt) {
                    mma_bf16(acc[mt][2*p],   aH[mt], rH[0], rH[1]);
                    mma_bf16(acc[mt][2*p],   aH[mt], rL[0], rL[1]);
                    mma_bf16(acc[mt][2*p],   aL[mt], rH[0], rH[1]);
                    mma_bf16(acc[mt][2*p+1], aH[mt], rH[2], rH[3]);
                    mma_bf16(acc[mt][2*p+1], aH[mt], rL[2], rL[3]);
                    mma_bf16(acc[mt][2*p+1], aL[mt], rH[2], rH[3]);
                }
            }
        }
        __syncthreads();
        buf ^= 1;
    }

    if (EPI == 0) {
        #pragma unroll
        for (int mt = 0; mt < 2; ++mt) {
            int r0 = m0 + warp_m*32 + mt*16 + (lane >> 2);
            #pragma unroll
            for (int nt = 0; nt < NT; ++nt) {
                int c0 = n0 + warp_n*WN + nt*8 + ((lane & 3) << 1);
                *reinterpret_cast<float2*>(C + (size_t)r0*ldc + c0) =
                    make_float2(acc[mt][nt][0], acc[mt][nt][1]);
                *reinterpret_cast<float2*>(C + (size_t)(r0+8)*ldc + c0) =
                    make_float2(acc[mt][nt][2], acc[mt][nt][3]);
            }
        }
    } else {
        // ===== fused conv + silu epilogue (BN==64 path) =====
        float* sf = reinterpret_cast<float*>(smem);
        #pragma unroll
        for (int mt = 0; mt < 2; ++mt) {
            int r0 = warp_m*32 + mt*16 + (lane >> 2);
            #pragma unroll
            for (int nt = 0; nt < NT; ++nt) {
                int c0 = warp_n*WN + nt*8 + ((lane & 3) << 1);
                *reinterpret_cast<float2*>(sf + (3+r0)*66 + c0) =
                    make_float2(acc[mt][nt][0], acc[mt][nt][1]);
                *reinterpret_cast<float2*>(sf + (11+r0)*66 + c0) =
                    make_float2(acc[mt][nt][2], acc[mt][nt][3]);
            }
        }
        if (tid < 192) {
            int r = tid / 64, c = tid - (tid/64)*64;
            float v = 0.f;
            if ((m0 & (SEQ-1)) != 0) {
                const float* xr = xsrc + (size_t)(m0 - 3 + r)*DMODEL;
                const float* wr = winsrc + (size_t)(n0 + c)*DMODEL;
                float a0 = 0.f, a1 = 0.f, a2 = 0.f, a3 = 0.f;
                #pragma unroll 4
                for (int k = 0; k < DMODEL; k += 4) {
                    float4 xv = *reinterpret_cast<const float4*>(xr + k);
                    float4 wv = *reinterpret_cast<const float4*>(wr + k);
                    a0 = fmaf(xv.x, wv.x, a0);
                    a1 = fmaf(xv.y, wv.y, a1);
                    a2 = fmaf(xv.z, wv.z, a2);
                    a3 = fmaf(xv.w, wv.w, a3);
                }
                v = (a0 + a1) + (a2 + a3);
            }
            sf[r*66 + c] = v;
        }
        __syncthreads();

        const int cpair = tid & 31;
        const int tg = tid >> 5;
        const int c = cpair << 1;
        const float4 w0 = reinterpret_cast<const float4*>(conv_w)[n0 + c];
        const float4 w1 = reinterpret_cast<const float4*>(conv_w)[n0 + c + 1];
        const float b0 = conv_b[n0 + c], b1 = conv_b[n0 + c + 1];
        const int t0 = tg << 4;

        float2 p0 = *reinterpret_cast<float2*>(sf + (t0+0)*66 + c);
        float2 p1 = *reinterpret_cast<float2*>(sf + (t0+1)*66 + c);
        float2 p2 = *reinterpret_cast<float2*>(sf + (t0+2)*66 + c);
        #pragma unroll 4
        for (int i = 0; i < 16; ++i) {
            float2 p3 = *reinterpret_cast<float2*>(sf + (t0+3+i)*66 + c);
            float a0 = b0 + w0.x*p0.x + w0.y*p1.x + w0.z*p2.x + w0.w*p3.x;
            float a1 = b1 + w1.x*p0.y + w1.y*p1.y + w1.z*p2.y + w1.w*p3.y;
            a0 = a0 / (1.f + __expf(-a0));
            a1 = a1 / (1.f + __expf(-a1));
            float h0 = __bfloat162float(__float2bfloat16(a0));
            float h1 = __bfloat162float(__float2bfloat16(a1));
            size_t o = (size_t)(m0 + t0 + i)*DINNER + n0 + c;
            *reinterpret_cast<uint32_t*>(g_xch + o) = pack_bf16x2(a0, a1);
            *reinterpret_cast<uint32_t*>(g_xcl + o) = pack_bf16x2(a0 - h0, a1 - h1);
            p0 = p1; p1 = p2; p2 = p3;
        }
    }
}

// ---------------- dt + du (ILP-widened: 4-way split dot, 2 tokens in flight) --
__global__ __launch_bounds__(256)
void dtdu_kernel(const float* __restrict__ W_dt, const float* __restrict__ b_dt)
{
    const int c  = blockIdx.x * 256 + threadIdx.x;   // channel
    const int m0 = blockIdx.y * 32;                  // token group
    const int tid = threadIdx.x;

    float w[DTRANK];
    #pragma unroll
    for (int k = 0; k < DTRANK; k += 4) {
        float4 v = *reinterpret_cast<const float4*>(W_dt + (size_t)c*DTRANK + k);
        w[k] = v.x; w[k+1] = v.y; w[k+2] = v.z; w[k+3] = v.w;
    }
    const float bias = b_dt[c];

    __shared__ __align__(16) float s_r[32][36];   // 16B-multiple pitch
    #pragma unroll
    for (int i = 0; i < 4; ++i) {
        int e = tid + i*256;
        int tt = e >> 5, r = e & 31;
        int g = (m0 + tt)*NDBC + r;
        s_r[tt][r] = (g_dbcp[0][g] + g_dbcp[1][g]) + (g_dbcp[2][g] + g_dbcp[3][g]);
    }
    __syncthreads();

    #pragma unroll
    for (int tp = 0; tp < 16; ++tp) {            // 2 tokens per iteration
        const int ta = 2*tp, tb = 2*tp + 1;
        float a0 = bias, a1 = 0.f, a2 = 0.f, a3 = 0.f;   // token a, 4-way split
        float b0 = bias, b1 = 0.f, b2 = 0.f, b3 = 0.f;   // token b, 4-way split
        #pragma unroll
        for (int k = 0; k < DTRANK; k += 16) {
            float4 ra0 = *reinterpret_cast<const float4*>(&s_r[ta][k]);
            float4 ra1 = *reinterpret_cast<const float4*>(&s_r[ta][k+4]);
            float4 ra2 = *reinterpret_cast<const float4*>(&s_r[ta][k+8]);
            float4 ra3 = *reinterpret_cast<const float4*>(&s_r[ta][k+12]);
            float4 rb0 = *reinterpret_cast<const float4*>(&s_r[tb][k]);
            float4 rb1 = *reinterpret_cast<const float4*>(&s_r[tb][k+4]);
            float4 rb2 = *reinterpret_cast<const float4*>(&s_r[tb][k+8]);
            float4 rb3 = *reinterpret_cast<const float4*>(&s_r[tb][k+12]);
            a0 = fmaf(ra0.x, w[k+0],  a0);  a0 = fmaf(ra0.y, w[k+1],  a0);
            a1 = fmaf(ra0.z, w[k+2],  a1);  a1 = fmaf(ra0.w, w[k+3],  a1);
            a2 = fmaf(ra1.x, w[k+4],  a2);  a2 = fmaf(ra1.y, w[k+5],  a2);
            a3 = fmaf(ra1.z, w[k+6],  a3);  a3 = fmaf(ra1.w, w[k+7],  a3);
            a0 = fmaf(ra2.x, w[k+8],  a0);  a0 = fmaf(ra2.y, w[k+9],  a0);
            a1 = fmaf(ra2.z, w[k+10], a1);  a1 = fmaf(ra2.w, w[k+11], a1);
            a2 = fmaf(ra3.x, w[k+12], a2);  a2 = fmaf(ra3.y, w[k+13], a2);
            a3 = fmaf(ra3.z, w[k+14], a3);  a3 = fmaf(ra3.w, w[k+15], a3);
            b0 = fmaf(rb0.x, w[k+0],  b0);  b0 = fmaf(rb0.y, w[k+1],  b0);
            b1 = fmaf(rb0.z, w[k+2],  b1);  b1 = fmaf(rb0.w, w[k+3],  b1);
            b2 = fmaf(rb1.x, w[k+4],  b2);  b2 = fmaf(rb1.y, w[k+5],  b2);
            b3 = fmaf(rb1.z, w[k+6],  b3);  b3 = fmaf(rb1.w, w[k+7],  b3);
            b0 = fmaf(rb2.x, w[k+8],  b0);  b0 = fmaf(rb2.y, w[k+9],  b0);
            b1 = fmaf(rb2.z, w[k+10], b1);  b1 = fmaf(rb2.w, w[k+11], b1);
            b2 = fmaf(rb3.x, w[k+12], b2);  b2 = fmaf(rb3.y, w[k+13], b2);
            b3 = fmaf(rb3.z, w[k+14], b3);  b3 = fmaf(rb3.w, w[k+15], b3);
        }
        float sa = (a0 + a1) + (a2 + a3);
        float sb = (b0 + b1) + (b2 + b3);
        float dta = (sa > 15.f) ? sa : __logf(1.f + __expf(sa));
        float dtb = (sb > 15.f) ? sb : __logf(1.f + __expf(sb));
        size_t oa = (size_t)(m0 + ta)*DINNER + c;
        size_t ob = (size_t)(m0 + tb)*DINNER + c;
        float ua = __bfloat162float(g_xch[oa]) + __bfloat162float(g_xcl[oa]);
        float ub = __bfloat162float(g_xch[ob]) + __bfloat162float(g_xcl[ob]);
        g_dt[oa] = dta;  g_du[oa] = dta * ua;
        g_dt[ob] = dtb;  g_du[ob] = dtb * ub;
    }
}

// ---------------- selective scan (loads precomputed dt/du; fused zlast) -------
__global__ __launch_bounds__(256)
void scan_kernel(const float* __restrict__ A_log,
                 const float* __restrict__ Dv,
                 const float* __restrict__ x,
                 const float* __restrict__ W_in)
{
    const int b     = blockIdx.x >> 6;
    const int dbase = (blockIdx.x & 63) << 4;
    const int tid = threadIdx.x;
    const int dl  = tid >> 4;    // 0..15 local channel
    const int s   = tid & 15;    // state
    const int d   = dbase + dl;

    __shared__ float s_z[16];
    __shared__ __align__(16) float s_dtT[16][68];
    __shared__ __align__(16) float s_duT[16][68];
    __shared__ __align__(16) float s_BT [16][68];

    // fused zlast
    {
        const float* xr = x + ((size_t)b*SEQ + (SEQ-1))*DMODEL + s*32;
        const float* wr = W_in + (size_t)(DINNER + dbase + dl)*DMODEL + s*32;
        float a0 = 0.f, a1 = 0.f, a2 = 0.f, a3 = 0.f;
        #pragma unroll
        for (int k = 0; k < 32; k += 4) {
            float4 xv = *reinterpret_cast<const float4*>(xr + k);
            float4 wv = *reinterpret_cast<const float4*>(wr + k);
            a0 = fmaf(xv.x, wv.x, a0);
            a1 = fmaf(xv.y, wv.y, a1);
            a2 = fmaf(xv.z, wv.z, a2);
            a3 = fmaf(xv.w, wv.w, a3);
        }
        float acc = (a0 + a1) + (a2 + a3);
        #pragma unroll
        for (int off = 8; off; off >>= 1)
            acc += __shfl_down_sync(0xffffffffu, acc, off, 16);
        if (s == 0) s_z[dl] = acc;
    }

    const float A2_s = -__expf(A_log[d*DSTATE + s]) * 1.44269504f;
    float h = 0.f;

    for (int t0 = 0; t0 < SEQ; t0 += 64) {
        __syncthreads();
        #pragma unroll
        for (int i = 0; i < 4; ++i) {
            int idx = tid + i*256;
            int tt = idx >> 4, c = idx & 15;
            int m = b*SEQ + t0 + tt;
            size_t o = (size_t)m*DINNER + dbase + c;
            s_dtT[c][tt] = g_dt[o];
            s_duT[c][tt] = g_du[o];
            int g = m*NDBC + DTRANK + c;
            s_BT[c][tt] = (g_dbcp[0][g] + g_dbcp[1][g])
                        + (g_dbcp[2][g] + g_dbcp[3][g]);
        }
        __syncthreads();
        #pragma unroll
        for (int t4 = 0; t4 < 16; ++t4) {
            float4 dt4 = *reinterpret_cast<float4*>(&s_dtT[dl][t4*4]);
            float4 du4 = *reinterpret_cast<float4*>(&s_duT[dl][t4*4]);
            float4 B4  = *reinterpret_cast<float4*>(&s_BT [s][t4*4]);
            h = fmaf(ex2(dt4.x * A2_s), h, du4.x * B4.x);
            h = fmaf(ex2(dt4.y * A2_s), h, du4.y * B4.y);
            h = fmaf(ex2(dt4.z * A2_s), h, du4.z * B4.z);
            h = fmaf(ex2(dt4.w * A2_s), h, du4.w * B4.w);
        }
    }

    const int mlast = b*SEQ + (SEQ-1);
    int gc = mlast*NDBC + DTRANK + DSTATE + s;
    float Cv = (g_dbcp[0][gc] + g_dbcp[1][gc]) + (g_dbcp[2][gc] + g_dbcp[3][gc]);
    float y = h * Cv;
    #pragma unroll
    for (int off = 8; off; off >>= 1) y += __shfl_down_sync(0xffffffffu, y, off, 16);
    if (s == 0) {
        size_t o = (size_t)mlast*DINNER + d;
        float ul = __bfloat162float(g_xch[o]) + __bfloat162float(g_xcl[o]);
        float zl = s_z[dl];
        float silu_z = zl / (1.f + __expf(-zl));
        g_ylast[b*DINNER + d] = (y + Dv[d]*ul) * silu_z;
    }
}

// ---------------- out projection: last = ylast @ W_out^T ----------------------
__global__ __launch_bounds__(256)
void outproj_kernel(const float* __restrict__ W_out)
{
    const int j = blockIdx.x;
    __shared__ float w[DINNER];
    for (int i = threadIdx.x; i < DINNER; i += 256)
        w[i] = W_out[(size_t)j*DINNER + i];
    __syncthreads();
    const int b = threadIdx.x >> 5;
    const int lane = threadIdx.x & 31;
    float acc = 0.f;
    #pragma unroll 8
    for (int k = lane; k < DINNER; k += 32)
        acc = fmaf(g_ylast[b*DINNER + k], w[k], acc);
    #pragma unroll
    for (int off = 16; off; off >>= 1) acc += __shfl_down_sync(0xffffffffu, acc, off);
    if (lane == 0) g_last[b*DMODEL + j] = acc;
}

// ---------------- layernorm ----------------------------------------------------
__global__ void ln_kernel(const float* __restrict__ ln_g,
                          const float* __restrict__ ln_b)
{
    const int b = blockIdx.x;
    const int j = threadIdx.x;
    __shared__ float rbuf[DMODEL];
    float v = g_last[b*DMODEL + j];
    rbuf[j] = v;
    __syncthreads();
    #pragma unroll
    for (int st = 256; st > 0; st >>= 1) {
        if (j < st) rbuf[j] += rbuf[j + st];
        __syncthreads();
    }
    float mu = rbuf[0] / (float)DMODEL;
    __syncthreads();
    float diff = v - mu;
    rbuf[j] = diff * diff;
    __syncthreads();
    #pragma unroll
    for (int st = 256; st > 0; st >>= 1) {
        if (j < st) rbuf[j] += rbuf[j + st];
        __syncthreads();
    }
    float rstd = rsqrtf(rbuf[0] / (float)DMODEL + 1e-5f);
    g_lastn[b*DMODEL + j] = diff * rstd * ln_g[j] + ln_b[j];
}

// ---------------- head: out = lastn @ head_W^T + head_b ------------------------
__global__ __launch_bounds__(256)
void head_kernel(const float* __restrict__ head_W,
                 const float* __restrict__ head_b,
                 float* __restrict__ out)
{
    const int j = blockIdx.x;
    __shared__ float w[DMODEL];
    for (int i = threadIdx.x; i < DMODEL; i += 256)
        w[i] = head_W[(size_t)j*DMODEL + i];
    __syncthreads();
    const int b = threadIdx.x >> 5;
    const int lane = threadIdx.x & 31;
    float acc = 0.f;
    #pragma unroll 4
    for (int k = lane; k < DMODEL; k += 32)
        acc = fmaf(g_lastn[b*DMODEL + k], w[k], acc);
    #pragma unroll
    for (int off = 16; off; off >>= 1) acc += __shfl_down_sync(0xffffffffu, acc, off);
    if (lane == 0) out[b*DMODEL + j] = acc + head_b[j];
}

// ---------------- launch --------------------------------------------------------
extern "C" void kernel_launch(void* const* d_in, const int* in_sizes, int n_in,
                              void* d_out, int out_size)
{
    const float* x      = (const float*)d_in[0];
    const float* W_in   = (const float*)d_in[1];
    const float* conv_w = (const float*)d_in[2];
    const float* conv_b = (const float*)d_in[3];
    const float* W_x    = (const float*)d_in[4];
    const float* W_dt   = (const float*)d_in[5];
    const float* b_dt   = (const float*)d_in[6];
    const float* A_log  = (const float*)d_in[7];
    const float* Dv     = (const float*)d_in[8];
    const float* W_out  = (const float*)d_in[9];
    const float* ln_g   = (const float*)d_in[10];
    const float* ln_b   = (const float*)d_in[11];
    const float* head_W = (const float*)d_in[12];
    const float* head_b = (const float*)d_in[13];
    float* out = (float*)d_out;

    float *dbcp0, *dbcp1, *dbcp2, *dbcp3;
    cudaGetSymbolAddress((void**)&dbcp0, g_dbcp);
    dbcp1 = dbcp0 + MTOK*NDBC;
    dbcp2 = dbcp1 + MTOK*NDBC;
    dbcp3 = dbcp2 + MTOK*NDBC;
    __nv_bfloat16 *xh, *xl, *wih, *wil, *wxh, *wxl, *xch, *xcl;
    cudaGetSymbolAddress((void**)&xh,  g_xh);
    cudaGetSymbolAddress((void**)&xl,  g_xl);
    cudaGetSymbolAddress((void**)&wih, g_wih);
    cudaGetSymbolAddress((void**)&wil, g_wil);
    cudaGetSymbolAddress((void**)&wxh, g_wxh);
    cudaGetSymbolAddress((void**)&wxl, g_wxl);
    cudaGetSymbolAddress((void**)&xch, g_xch);
    cudaGetSymbolAddress((void**)&xcl, g_xcl);

    const int SMEM2 = (2*128*40 + 2*64*40) * 2 * 2;   // 61440
    cudaFuncSetAttribute((const void*)gemm_bs<64,0>,
                         cudaFuncAttributeMaxDynamicSharedMemorySize, SMEM2);
    cudaFuncSetAttribute((const void*)gemm_bs<64,1>,
                         cudaFuncAttributeMaxDynamicSharedMemorySize, SMEM2);

    // #0: split x, W_in[:1024], W_x into bf16 hi/lo
    {
        const int NT4 = MTOK*DMODEL/4 + DINNER*DMODEL/4 + NDBC*DINNER/4;
        split3_kernel<<<(NT4 + 255)/256, 256>>>(x, W_in, W_x);
    }

    // #1: K1 + fused conv/silu -> xch/xcl
    gemm_bs<64,1><<<dim3(DINNER/64, MTOK/128, 1), 256, SMEM2>>>(
        xh, xl, wih, wil, nullptr, nullptr, nullptr, nullptr,
        DMODEL, DMODEL, DMODEL, 0, x, W_in, conv_w, conv_b);

    // #2: K3: dbc partials = xc @ W_x.T, K split x4
    gemm_bs<64,0><<<dim3(1, MTOK/128, 4), 256, SMEM2>>>(
        xch, xcl, wxh, wxl, dbcp0, dbcp1, dbcp2, dbcp3,
        DINNER/4, DINNER, DINNER, NDBC, nullptr, nullptr, nullptr, nullptr);

    // #3 (ncu target): dt + du precompute (ILP-widened)
    dtdu_kernel<<<dim3(DINNER/256, MTOK/32), 256>>>(W_dt, b_dt);

    // #4: selective scan
    scan_kernel<<<BATCH * (DINNER/16), 256>>>(A_log, Dv, x, W_in);

    // #5-#7: out projection, layernorm, head
    outproj_kernel<<<DMODEL, 256>>>(W_out);
    ln_kernel<<<BATCH, DMODEL>>>(ln_g, ln_b);
    head_kernel<<<DMODEL, 256>>>(head_W, head_b, out);
}

// round 16
// speedup vs baseline: 1.0759x; 1.0040x over previous
#include <cuda_runtime.h>
#include <cuda_bf16.h>
#include <cstdint>

#define BATCH   8
#define SEQ     1024
#define DMODEL  512
#define DINNER  1024
#define DSTATE  16
#define DTRANK  32
#define DCONV   4
#define MTOK    (BATCH*SEQ)
#define NDBC    (DTRANK + 2*DSTATE)

// ---------------- scratch -----------------------------------------------------
__device__ float g_dbcp[4][MTOK * NDBC];
__device__ float g_dt [MTOK * DINNER];
__device__ float g_ylast[BATCH * DINNER];
__device__ float g_last [BATCH * DMODEL];
__device__ float g_lastn[BATCH * DMODEL];
__device__ __nv_bfloat16 g_xh [MTOK * DMODEL];
__device__ __nv_bfloat16 g_xl [MTOK * DMODEL];
__device__ __nv_bfloat16 g_wih[DINNER * DMODEL];
__device__ __nv_bfloat16 g_wil[DINNER * DMODEL];
__device__ __nv_bfloat16 g_wxh[NDBC * DINNER];
__device__ __nv_bfloat16 g_wxl[NDBC * DINNER];
__device__ __nv_bfloat16 g_xch[MTOK * DINNER];
__device__ __nv_bfloat16 g_xcl[MTOK * DINNER];

// ======================= helpers ==============================================
__device__ __forceinline__ uint32_t smem_u32(const void* p) {
    uint32_t a;
    asm("{ .reg .u64 t; cvta.to.shared.u64 t, %1; cvt.u32.u64 %0, t; }" : "=r"(a) : "l"(p));
    return a;
}
__device__ __forceinline__ void ldsm4(uint32_t* r, uint32_t addr) {
    asm volatile("ldmatrix.sync.aligned.m8n8.x4.shared.b16 {%0,%1,%2,%3}, [%4];"
                 : "=r"(r[0]), "=r"(r[1]), "=r"(r[2]), "=r"(r[3]) : "r"(addr));
}
__device__ __forceinline__ void mma_bf16(float* d, const uint32_t* a,
                                         uint32_t b0, uint32_t b1) {
    asm volatile("mma.sync.aligned.m16n8k16.row.col.f32.bf16.bf16.f32 "
                 "{%0,%1,%2,%3}, {%4,%5,%6,%7}, {%8,%9}, {%0,%1,%2,%3};"
                 : "+f"(d[0]), "+f"(d[1]), "+f"(d[2]), "+f"(d[3])
                 : "r"(a[0]), "r"(a[1]), "r"(a[2]), "r"(a[3]), "r"(b0), "r"(b1));
}
__device__ __forceinline__ uint32_t pack_bf16x2(float x, float y) {
    __nv_bfloat16 hx = __float2bfloat16(x), hy = __float2bfloat16(y);
    return ((uint32_t)__bfloat16_as_ushort(hy) << 16) | (uint32_t)__bfloat16_as_ushort(hx);
}
__device__ __forceinline__ void cp16(uint32_t dst, const void* src) {
    asm volatile("cp.async.cg.shared.global [%0], [%1], 16;" :: "r"(dst), "l"(src));
}
__device__ __forceinline__ float ex2(float x) {
    float r;
    asm("ex2.approx.f32 %0, %1;" : "=f"(r) : "f"(x));
    return r;
}
#define CP_COMMIT() asm volatile("cp.async.commit_group;" ::: "memory")
#define CP_WAIT1()  asm volatile("cp.async.wait_group 1;" ::: "memory")

// ---------------- fp32 -> bf16 hi/lo split ------------------------------------
__global__ void split_kernel(const float* __restrict__ src,
                             __nv_bfloat16* __restrict__ hi,
                             __nv_bfloat16* __restrict__ lo, int n4)
{
    int i = blockIdx.x * blockDim.x + threadIdx.x;
    if (i >= n4) return;
    float4 v = reinterpret_cast<const float4*>(src)[i];
    float hx = __bfloat162float(__float2bfloat16(v.x));
    float hy = __bfloat162float(__float2bfloat16(v.y));
    float hz = __bfloat162float(__float2bfloat16(v.z));
    float hw = __bfloat162float(__float2bfloat16(v.w));
    reinterpret_cast<uint2*>(hi)[i] =
        make_uint2(pack_bf16x2(v.x, v.y), pack_bf16x2(v.z, v.w));
    reinterpret_cast<uint2*>(lo)[i] =
        make_uint2(pack_bf16x2(v.x - hx, v.y - hy), pack_bf16x2(v.z - hz, v.w - hw));
}

// ====== pipelined bf16 split GEMM, 2-stage cp.async, block 128x64 =============
template<int BN, int EPI>
__global__ __launch_bounds__(256)
void gemm_bs(const __nv_bfloat16* __restrict__ Ah, const __nv_bfloat16* __restrict__ Al,
             const __nv_bfloat16* __restrict__ Bh, const __nv_bfloat16* __restrict__ Bl,
             float* __restrict__ C0, float* __restrict__ C1,
             float* __restrict__ C2, float* __restrict__ C3,
             int kspan, int lda, int ldb, int ldc,
             const float* __restrict__ xsrc, const float* __restrict__ winsrc,
             const float* __restrict__ conv_w, const float* __restrict__ conv_b)
{
    constexpr int BM = 128, BK = 32;
    constexpr int WN = BN / 2;
    constexpr int NT = WN / 8;
    constexpr int PITCH = BK + 8;
    constexpr int OFF_AH = 0;
    constexpr int OFF_AL = BM*PITCH;
    constexpr int OFF_BH = 2*BM*PITCH;
    constexpr int OFF_BL = 2*BM*PITCH + BN*PITCH;
    constexpr int STAGE  = 2*BM*PITCH + 2*BN*PITCH;

    extern __shared__ __align__(16) uint16_t smem[];
    const uint32_t sbase = smem_u32(smem);

    const int tid  = threadIdx.x;
    const int wid  = tid >> 5;
    const int lane = tid & 31;
    const int warp_m = wid & 3;
    const int warp_n = wid >> 2;
    const int m0 = blockIdx.y * BM;
    const int n0 = blockIdx.x * BN;
    const int kbeg = blockIdx.z * kspan;
    const int kend = kbeg + kspan;
    float* C = (blockIdx.z == 0) ? C0 : (blockIdx.z == 1) ? C1
             : (blockIdx.z == 2) ? C2 : C3;

    const int ld_r = tid >> 2;
    const int ld_c = (tid & 3) << 3;

    float acc[2][NT][4];
    #pragma unroll
    for (int mt = 0; mt < 2; ++mt)
        #pragma unroll
        for (int nt = 0; nt < NT; ++nt)
            #pragma unroll
            for (int j = 0; j < 4; ++j) acc[mt][nt][j] = 0.f;

    const int a_row = (lane & 15);
    const int a_koff = (lane >> 4) << 3;
    const int b_row = ((lane >> 4) << 3) + (lane & 7);
    const int b_koff = ((lane >> 3) & 1) << 3;

    auto load_stage = [&](int s, int k0) {
        uint32_t base = sbase + (uint32_t)(s*STAGE*2);
        #pragma unroll
        for (int i = 0; i < 2; ++i) {
            int r = ld_r + i*64;
            uint32_t so = base + (uint32_t)((r*PITCH + ld_c)*2);
            cp16(so + OFF_AH*2, Ah + (size_t)(m0+r)*lda + k0 + ld_c);
            cp16(so + OFF_AL*2, Al + (size_t)(m0+r)*lda + k0 + ld_c);
            if (i*64 < BN) {
                cp16(so + OFF_BH*2, Bh + (size_t)(n0+r)*ldb + k0 + ld_c);
                cp16(so + OFF_BL*2, Bl + (size_t)(n0+r)*ldb + k0 + ld_c);
            }
        }
    };

    load_stage(0, kbeg);
    CP_COMMIT();

    int buf = 0;
    for (int k0 = kbeg; k0 < kend; k0 += BK) {
        if (k0 + BK < kend) load_stage(buf ^ 1, k0 + BK);
        CP_COMMIT();
        CP_WAIT1();
        __syncthreads();

        const uint32_t stg = sbase + (uint32_t)(buf*STAGE*2);
        #pragma unroll
        for (int kstep = 0; kstep < 2; ++kstep) {
            uint32_t aH[2][4], aL[2][4];
            #pragma unroll
            for (int mt = 0; mt < 2; ++mt) {
                uint32_t off = (uint32_t)(((warp_m*32 + mt*16 + a_row)*PITCH
                                          + kstep*16 + a_koff) * 2);
                ldsm4(aH[mt], stg + OFF_AH*2 + off);
                ldsm4(aL[mt], stg + OFF_AL*2 + off);
            }
            #pragma unroll
            for (int p = 0; p < NT/2; ++p) {
                uint32_t off = (uint32_t)(((warp_n*WN + p*16 + b_row)*PITCH
                                          + kstep*16 + b_koff) * 2);
                uint32_t rH[4], rL[4];
                ldsm4(rH, stg + OFF_BH*2 + off);
                ldsm4(rL, stg + OFF_BL*2 + off);
                #pragma unroll
                for (int mt = 0; mt < 2; ++mt) {
                    mma_bf16(acc[mt][2*p],   aH[mt], rH[0], rH[1]);
                    mma_bf16(acc[mt][2*p],   aH[mt], rL[0], rL[1]);
                    mma_bf16(acc[mt][2*p],   aL[mt], rH[0], rH[1]);
                    mma_bf16(acc[mt][2*p+1], aH[mt], rH[2], rH[3]);
                    mma_bf16(acc[mt][2*p+1], aH[mt], rL[2], rL[3]);
                    mma_bf16(acc[mt][2*p+1], aL[mt], rH[2], rH[3]);
                }
            }
        }
        __syncthreads();
        buf ^= 1;
    }

    if (EPI == 0) {
        #pragma unroll
        for (int mt = 0; mt < 2; ++mt) {
            int r0 = m0 + warp_m*32 + mt*16 + (lane >> 2);
            #pragma unroll
            for (int nt = 0; nt < NT; ++nt) {
                int c0 = n0 + warp_n*WN + nt*8 + ((lane & 3) << 1);
                *reinterpret_cast<float2*>(C + (size_t)r0*ldc + c0) =
                    make_float2(acc[mt][nt][0], acc[mt][nt][1]);
                *reinterpret_cast<float2*>(C + (size_t)(r0+8)*ldc + c0) =
                    make_float2(acc[mt][nt][2], acc[mt][nt][3]);
            }
        }
    } else {
        // ===== fused conv + silu epilogue (BN==64 path) =====
        float* sf = reinterpret_cast<float*>(smem);
        #pragma unroll
        for (int mt = 0; mt < 2; ++mt) {
            int r0 = warp_m*32 + mt*16 + (lane >> 2);
            #pragma unroll
            for (int nt = 0; nt < NT; ++nt) {
                int c0 = warp_n*WN + nt*8 + ((lane & 3) << 1);
                *reinterpret_cast<float2*>(sf + (3+r0)*66 + c0) =
                    make_float2(acc[mt][nt][0], acc[mt][nt][1]);
                *reinterpret_cast<float2*>(sf + (11+r0)*66 + c0) =
                    make_float2(acc[mt][nt][2], acc[mt][nt][3]);
            }
        }
        if (tid < 192) {
            int r = tid / 64, c = tid - (tid/64)*64;
            float v = 0.f;
            if ((m0 & (SEQ-1)) != 0) {
                const float* xr = xsrc + (size_t)(m0 - 3 + r)*DMODEL;
                const float* wr = winsrc + (size_t)(n0 + c)*DMODEL;
                float a0 = 0.f, a1 = 0.f, a2 = 0.f, a3 = 0.f;
                #pragma unroll 4
                for (int k = 0; k < DMODEL; k += 4) {
                    float4 xv = *reinterpret_cast<const float4*>(xr + k);
                    float4 wv = *reinterpret_cast<const float4*>(wr + k);
                    a0 = fmaf(xv.x, wv.x, a0);
                    a1 = fmaf(xv.y, wv.y, a1);
                    a2 = fmaf(xv.z, wv.z, a2);
                    a3 = fmaf(xv.w, wv.w, a3);
                }
                v = (a0 + a1) + (a2 + a3);
            }
            sf[r*66 + c] = v;
        }
        __syncthreads();

        const int cpair = tid & 31;
        const int tg = tid >> 5;
        const int c = cpair << 1;
        const float4 w0 = reinterpret_cast<const float4*>(conv_w)[n0 + c];
        const float4 w1 = reinterpret_cast<const float4*>(conv_w)[n0 + c + 1];
        const float b0 = conv_b[n0 + c], b1 = conv_b[n0 + c + 1];
        const int t0 = tg << 4;

        float2 p0 = *reinterpret_cast<float2*>(sf + (t0+0)*66 + c);
        float2 p1 = *reinterpret_cast<float2*>(sf + (t0+1)*66 + c);
        float2 p2 = *reinterpret_cast<float2*>(sf + (t0+2)*66 + c);
        #pragma unroll 4
        for (int i = 0; i < 16; ++i) {
            float2 p3 = *reinterpret_cast<float2*>(sf + (t0+3+i)*66 + c);
            float a0 = b0 + w0.x*p0.x + w0.y*p1.x + w0.z*p2.x + w0.w*p3.x;
            float a1 = b1 + w1.x*p0.y + w1.y*p1.y + w1.z*p2.y + w1.w*p3.y;
            a0 = a0 / (1.f + __expf(-a0));
            a1 = a1 / (1.f + __expf(-a1));
            float h0 = __bfloat162float(__float2bfloat16(a0));
            float h1 = __bfloat162float(__float2bfloat16(a1));
            size_t o = (size_t)(m0 + t0 + i)*DINNER + n0 + c;
            *reinterpret_cast<uint32_t*>(g_xch + o) = pack_bf16x2(a0, a1);
            *reinterpret_cast<uint32_t*>(g_xcl + o) = pack_bf16x2(a0 - h0, a1 - h1);
            p0 = p1; p1 = p2; p2 = p3;
        }
    }
}

// ---------------- dt only: dt = softplus(dbc[:,:32]@W_dt^T + b_dt) ------------
// du moved into scan staging; this kernel's traffic is 40MB instead of 104MB.
__global__ __launch_bounds__(256)
void dt_kernel(const float* __restrict__ W_dt, const float* __restrict__ b_dt)
{
    const int c  = blockIdx.x * 256 + threadIdx.x;   // channel
    const int m0 = blockIdx.y * 32;                  // token group
    const int tid = threadIdx.x;

    float w[DTRANK];
    #pragma unroll
    for (int k = 0; k < DTRANK; k += 4) {
        float4 v = *reinterpret_cast<const float4*>(W_dt + (size_t)c*DTRANK + k);
        w[k] = v.x; w[k+1] = v.y; w[k+2] = v.z; w[k+3] = v.w;
    }
    const float bias = b_dt[c];

    __shared__ __align__(16) float s_r[32][36];   // 16B-multiple pitch
    #pragma unroll
    for (int i = 0; i < 4; ++i) {
        int e = tid + i*256;
        int tt = e >> 5, r = e & 31;
        int g = (m0 + tt)*NDBC + r;
        s_r[tt][r] = (g_dbcp[0][g] + g_dbcp[1][g]) + (g_dbcp[2][g] + g_dbcp[3][g]);
    }
    __syncthreads();

    #pragma unroll
    for (int tp = 0; tp < 16; ++tp) {            // 2 tokens per iteration
        const int ta = 2*tp, tb = 2*tp + 1;
        float a0 = bias, a1 = 0.f, a2 = 0.f, a3 = 0.f;
        float b0 = bias, b1 = 0.f, b2 = 0.f, b3 = 0.f;
        #pragma unroll
        for (int k = 0; k < DTRANK; k += 16) {
            float4 ra0 = *reinterpret_cast<const float4*>(&s_r[ta][k]);
            float4 ra1 = *reinterpret_cast<const float4*>(&s_r[ta][k+4]);
            float4 ra2 = *reinterpret_cast<const float4*>(&s_r[ta][k+8]);
            float4 ra3 = *reinterpret_cast<const float4*>(&s_r[ta][k+12]);
            float4 rb0 = *reinterpret_cast<const float4*>(&s_r[tb][k]);
            float4 rb1 = *reinterpret_cast<const float4*>(&s_r[tb][k+4]);
            float4 rb2 = *reinterpret_cast<const float4*>(&s_r[tb][k+8]);
            float4 rb3 = *reinterpret_cast<const float4*>(&s_r[tb][k+12]);
            a0 = fmaf(ra0.x, w[k+0],  a0);  a0 = fmaf(ra0.y, w[k+1],  a0);
            a1 = fmaf(ra0.z, w[k+2],  a1);  a1 = fmaf(ra0.w, w[k+3],  a1);
            a2 = fmaf(ra1.x, w[k+4],  a2);  a2 = fmaf(ra1.y, w[k+5],  a2);
            a3 = fmaf(ra1.z, w[k+6],  a3);  a3 = fmaf(ra1.w, w[k+7],  a3);
            a0 = fmaf(ra2.x, w[k+8],  a0);  a0 = fmaf(ra2.y, w[k+9],  a0);
            a1 = fmaf(ra2.z, w[k+10], a1);  a1 = fmaf(ra2.w, w[k+11], a1);
            a2 = fmaf(ra3.x, w[k+12], a2);  a2 = fmaf(ra3.y, w[k+13], a2);
            a3 = fmaf(ra3.z, w[k+14], a3);  a3 = fmaf(ra3.w, w[k+15], a3);
            b0 = fmaf(rb0.x, w[k+0],  b0);  b0 = fmaf(rb0.y, w[k+1],  b0);
            b1 = fmaf(rb0.z, w[k+2],  b1);  b1 = fmaf(rb0.w, w[k+3],  b1);
            b2 = fmaf(rb1.x, w[k+4],  b2);  b2 = fmaf(rb1.y, w[k+5],  b2);
            b3 = fmaf(rb1.z, w[k+6],  b3);  b3 = fmaf(rb1.w, w[k+7],  b3);
            b0 = fmaf(rb2.x, w[k+8],  b0);  b0 = fmaf(rb2.y, w[k+9],  b0);
            b1 = fmaf(rb2.z, w[k+10], b1);  b1 = fmaf(rb2.w, w[k+11], b1);
            b2 = fmaf(rb3.x, w[k+12], b2);  b2 = fmaf(rb3.y, w[k+13], b2);
            b3 = fmaf(rb3.z, w[k+14], b3);  b3 = fmaf(rb3.w, w[k+15], b3);
        }
        float sa = (a0 + a1) + (a2 + a3);
        float sb = (b0 + b1) + (b2 + b3);
        g_dt[(size_t)(m0 + ta)*DINNER + c] =
            (sa > 15.f) ? sa : __logf(1.f + __expf(sa));
        g_dt[(size_t)(m0 + tb)*DINNER + c] =
            (sb > 15.f) ? sb : __logf(1.f + __expf(sb));
    }
}

// ---------------- selective scan (du computed in staging; fused zlast) --------
__global__ __launch_bounds__(256)
void scan_kernel(const float* __restrict__ A_log,
                 const float* __restrict__ Dv,
                 const float* __restrict__ x,
                 const float* __restrict__ W_in)
{
    const int b     = blockIdx.x >> 6;
    const int dbase = (blockIdx.x & 63) << 4;
    const int tid = threadIdx.x;
    const int dl  = tid >> 4;    // 0..15 local channel
    const int s   = tid & 15;    // state
    const int d   = dbase + dl;

    __shared__ float s_z[16];
    __shared__ __align__(16) float s_dtT[16][68];
    __shared__ __align__(16) float s_duT[16][68];
    __shared__ __align__(16) float s_BT [16][68];

    // fused zlast
    {
        const float* xr = x + ((size_t)b*SEQ + (SEQ-1))*DMODEL + s*32;
        const float* wr = W_in + (size_t)(DINNER + dbase + dl)*DMODEL + s*32;
        float a0 = 0.f, a1 = 0.f, a2 = 0.f, a3 = 0.f;
        #pragma unroll
        for (int k = 0; k < 32; k += 4) {
            float4 xv = *reinterpret_cast<const float4*>(xr + k);
            float4 wv = *reinterpret_cast<const float4*>(wr + k);
            a0 = fmaf(xv.x, wv.x, a0);
            a1 = fmaf(xv.y, wv.y, a1);
            a2 = fmaf(xv.z, wv.z, a2);
            a3 = fmaf(xv.w, wv.w, a3);
        }
        float acc = (a0 + a1) + (a2 + a3);
        #pragma unroll
        for (int off = 8; off; off >>= 1)
            acc += __shfl_down_sync(0xffffffffu, acc, off, 16);
        if (s == 0) s_z[dl] = acc;
    }

    const float A2_s = -__expf(A_log[d*DSTATE + s]) * 1.44269504f;
    float h = 0.f;

    for (int t0 = 0; t0 < SEQ; t0 += 64) {
        __syncthreads();
        #pragma unroll
        for (int i = 0; i < 4; ++i) {
            int idx = tid + i*256;
            int tt = idx >> 4, c = idx & 15;
            int m = b*SEQ + t0 + tt;
            size_t o = (size_t)m*DINNER + dbase + c;
            float dt = g_dt[o];
            float u  = __bfloat162float(g_xch[o]) + __bfloat162float(g_xcl[o]);
            s_dtT[c][tt] = dt;
            s_duT[c][tt] = dt * u;
            int g = m*NDBC + DTRANK + c;
            s_BT[c][tt] = (g_dbcp[0][g] + g_dbcp[1][g])
                        + (g_dbcp[2][g] + g_dbcp[3][g]);
        }
        __syncthreads();
        #pragma unroll
        for (int t4 = 0; t4 < 16; ++t4) {
            float4 dt4 = *reinterpret_cast<float4*>(&s_dtT[dl][t4*4]);
            float4 du4 = *reinterpret_cast<float4*>(&s_duT[dl][t4*4]);
            float4 B4  = *reinterpret_cast<float4*>(&s_BT [s][t4*4]);
            h = fmaf(ex2(dt4.x * A2_s), h, du4.x * B4.x);
            h = fmaf(ex2(dt4.y * A2_s), h, du4.y * B4.y);
            h = fmaf(ex2(dt4.z * A2_s), h, du4.z * B4.z);
            h = fmaf(ex2(dt4.w * A2_s), h, du4.w * B4.w);
        }
    }

    const int mlast = b*SEQ + (SEQ-1);
    int gc = mlast*NDBC + DTRANK + DSTATE + s;
    float Cv = (g_dbcp[0][gc] + g_dbcp[1][gc]) + (g_dbcp[2][gc] + g_dbcp[3][gc]);
    float y = h * Cv;
    #pragma unroll
    for (int off = 8; off; off >>= 1) y += __shfl_down_sync(0xffffffffu, y, off, 16);
    if (s == 0) {
        size_t o = (size_t)mlast*DINNER + d;
        float ul = __bfloat162float(g_xch[o]) + __bfloat162float(g_xcl[o]);
        float zl = s_z[dl];
        float silu_z = zl / (1.f + __expf(-zl));
        g_ylast[b*DINNER + d] = (y + Dv[d]*ul) * silu_z;
    }
}

// ---------------- out projection: last = ylast @ W_out^T ----------------------
__global__ __launch_bounds__(256)
void outproj_kernel(const float* __restrict__ W_out)
{
    const int j = blockIdx.x;
    __shared__ float w[DINNER];
    for (int i = threadIdx.x; i < DINNER; i += 256)
        w[i] = W_out[(size_t)j*DINNER + i];
    __syncthreads();
    const int b = threadIdx.x >> 5;
    const int lane = threadIdx.x & 31;
    float acc = 0.f;
    #pragma unroll 8
    for (int k = lane; k < DINNER; k += 32)
        acc = fmaf(g_ylast[b*DINNER + k], w[k], acc);
    #pragma unroll
    for (int off = 16; off; off >>= 1) acc += __shfl_down_sync(0xffffffffu, acc, off);
    if (lane == 0) g_last[b*DMODEL + j] = acc;
}

// ---------------- layernorm ----------------------------------------------------
__global__ void ln_kernel(const float* __restrict__ ln_g,
                          const float* __restrict__ ln_b)
{
    const int b = blockIdx.x;
    const int j = threadIdx.x;
    __shared__ float rbuf[DMODEL];
    float v = g_last[b*DMODEL + j];
    rbuf[j] = v;
    __syncthreads();
    #pragma unroll
    for (int st = 256; st > 0; st >>= 1) {
        if (j < st) rbuf[j] += rbuf[j + st];
        __syncthreads();
    }
    float mu = rbuf[0] / (float)DMODEL;
    __syncthreads();
    float diff = v - mu;
    rbuf[j] = diff * diff;
    __syncthreads();
    #pragma unroll
    for (int st = 256; st > 0; st >>= 1) {
        if (j < st) rbuf[j] += rbuf[j + st];
        __syncthreads();
    }
    float rstd = rsqrtf(rbuf[0] / (float)DMODEL + 1e-5f);
    g_lastn[b*DMODEL + j] = diff * rstd * ln_g[j] + ln_b[j];
}

// ---------------- head: out = lastn @ head_W^T + head_b ------------------------
__global__ __launch_bounds__(256)
void head_kernel(const float* __restrict__ head_W,
                 const float* __restrict__ head_b,
                 float* __restrict__ out)
{
    const int j = blockIdx.x;
    __shared__ float w[DMODEL];
    for (int i = threadIdx.x; i < DMODEL; i += 256)
        w[i] = head_W[(size_t)j*DMODEL + i];
    __syncthreads();
    const int b = threadIdx.x >> 5;
    const int lane = threadIdx.x & 31;
    float acc = 0.f;
    #pragma unroll 4
    for (int k = lane; k < DMODEL; k += 32)
        acc = fmaf(g_lastn[b*DMODEL + k], w[k], acc);
    #pragma unroll
    for (int off = 16; off; off >>= 1) acc += __shfl_down_sync(0xffffffffu, acc, off);
    if (lane == 0) out[b*DMODEL + j] = acc + head_b[j];
}

// ---------------- launch --------------------------------------------------------
extern "C" void kernel_launch(void* const* d_in, const int* in_sizes, int n_in,
                              void* d_out, int out_size)
{
    const float* x      = (const float*)d_in[0];
    const float* W_in   = (const float*)d_in[1];
    const float* conv_w = (const float*)d_in[2];
    const float* conv_b = (const float*)d_in[3];
    const float* W_x    = (const float*)d_in[4];
    const float* W_dt   = (const float*)d_in[5];
    const float* b_dt   = (const float*)d_in[6];
    const float* A_log  = (const float*)d_in[7];
    const float* Dv     = (const float*)d_in[8];
    const float* W_out  = (const float*)d_in[9];
    const float* ln_g   = (const float*)d_in[10];
    const float* ln_b   = (const float*)d_in[11];
    const float* head_W = (const float*)d_in[12];
    const float* head_b = (const float*)d_in[13];
    float* out = (float*)d_out;

    float *dbcp0, *dbcp1, *dbcp2, *dbcp3;
    cudaGetSymbolAddress((void**)&dbcp0, g_dbcp);
    dbcp1 = dbcp0 + MTOK*NDBC;
    dbcp2 = dbcp1 + MTOK*NDBC;
    dbcp3 = dbcp2 + MTOK*NDBC;
    __nv_bfloat16 *xh, *xl, *wih, *wil, *wxh, *wxl, *xch, *xcl;
    cudaGetSymbolAddress((void**)&xh,  g_xh);
    cudaGetSymbolAddress((void**)&xl,  g_xl);
    cudaGetSymbolAddress((void**)&wih, g_wih);
    cudaGetSymbolAddress((void**)&wil, g_wil);
    cudaGetSymbolAddress((void**)&wxh, g_wxh);
    cudaGetSymbolAddress((void**)&wxl, g_wxl);
    cudaGetSymbolAddress((void**)&xch, g_xch);
    cudaGetSymbolAddress((void**)&xcl, g_xcl);

    const int SMEM2 = (2*128*40 + 2*64*40) * 2 * 2;   // 61440
    cudaFuncSetAttribute((const void*)gemm_bs<64,0>,
                         cudaFuncAttributeMaxDynamicSharedMemorySize, SMEM2);
    cudaFuncSetAttribute((const void*)gemm_bs<64,1>,
                         cudaFuncAttributeMaxDynamicSharedMemorySize, SMEM2);

    // #0-#2: splits as separate launches (puts K1 at profiler slot #3)
    split_kernel<<<(MTOK*DMODEL/4 + 255)/256, 256>>>(x, xh, xl, MTOK*DMODEL/4);
    split_kernel<<<(DINNER*DMODEL/4 + 255)/256, 256>>>(W_in, wih, wil, DINNER*DMODEL/4);
    split_kernel<<<(NDBC*DINNER/4 + 255)/256, 256>>>(W_x, wxh, wxl, NDBC*DINNER/4);

    // #3 (ncu target): K1 + fused conv/silu -> xch/xcl
    gemm_bs<64,1><<<dim3(DINNER/64, MTOK/128, 1), 256, SMEM2>>>(
        xh, xl, wih, wil, nullptr, nullptr, nullptr, nullptr,
        DMODEL, DMODEL, DMODEL, 0, x, W_in, conv_w, conv_b);

    // #4: K3: dbc partials = xc @ W_x.T, K split x4
    gemm_bs<64,0><<<dim3(1, MTOK/128, 4), 256, SMEM2>>>(
        xch, xcl, wxh, wxl, dbcp0, dbcp1, dbcp2, dbcp3,
        DINNER/4, DINNER, DINNER, NDBC, nullptr, nullptr, nullptr, nullptr);

    // #5: dt precompute (write dt only; du folded into scan staging)
    dt_kernel<<<dim3(DINNER/256, MTOK/32), 256>>>(W_dt, b_dt);

    // #6: selective scan
    scan_kernel<<<BATCH * (DINNER/16), 256>>>(A_log, Dv, x, W_in);

    // #7-#9: out projection, layernorm, head
    outproj_kernel<<<DMODEL, 256>>>(W_out);
    ln_kernel<<<BATCH, DMODEL>>>(ln_g, ln_b);
    head_kernel<<<DMODEL, 256>>>(head_W, head_b, out);
}

// round 17
// speedup vs baseline: 1.3332x; 1.2391x over previous
#include <cuda_runtime.h>
#include <cuda_bf16.h>
#include <cstdint>

#define BATCH   8
#define SEQ     1024
#define DMODEL  512
#define DINNER  1024
#define DSTATE  16
#define DTRANK  32
#define DCONV   4
#define MTOK    (BATCH*SEQ)
#define NDBC    (DTRANK + 2*DSTATE)

// ---------------- scratch -----------------------------------------------------
__device__ float g_xi [MTOK * DINNER];
__device__ float g_dbcp[4][MTOK * NDBC];
__device__ float g_dt [MTOK * DINNER];
__device__ float g_ylast[BATCH * DINNER];
__device__ float g_last [BATCH * DMODEL];
__device__ float g_lastn[BATCH * DMODEL];
__device__ __nv_bfloat16 g_xh [MTOK * DMODEL];
__device__ __nv_bfloat16 g_xl [MTOK * DMODEL];
__device__ __nv_bfloat16 g_wih[DINNER * DMODEL];
__device__ __nv_bfloat16 g_wil[DINNER * DMODEL];
__device__ __nv_bfloat16 g_wxh[NDBC * DINNER];
__device__ __nv_bfloat16 g_wxl[NDBC * DINNER];
__device__ __nv_bfloat16 g_xch[MTOK * DINNER];
__device__ __nv_bfloat16 g_xcl[MTOK * DINNER];

// ======================= helpers ==============================================
__device__ __forceinline__ uint32_t smem_u32(const void* p) {
    uint32_t a;
    asm("{ .reg .u64 t; cvta.to.shared.u64 t, %1; cvt.u32.u64 %0, t; }" : "=r"(a) : "l"(p));
    return a;
}
__device__ __forceinline__ void ldsm4(uint32_t* r, uint32_t addr) {
    asm volatile("ldmatrix.sync.aligned.m8n8.x4.shared.b16 {%0,%1,%2,%3}, [%4];"
                 : "=r"(r[0]), "=r"(r[1]), "=r"(r[2]), "=r"(r[3]) : "r"(addr));
}
__device__ __forceinline__ void mma_bf16(float* d, const uint32_t* a,
                                         uint32_t b0, uint32_t b1) {
    asm volatile("mma.sync.aligned.m16n8k16.row.col.f32.bf16.bf16.f32 "
                 "{%0,%1,%2,%3}, {%4,%5,%6,%7}, {%8,%9}, {%0,%1,%2,%3};"
                 : "+f"(d[0]), "+f"(d[1]), "+f"(d[2]), "+f"(d[3])
                 : "r"(a[0]), "r"(a[1]), "r"(a[2]), "r"(a[3]), "r"(b0), "r"(b1));
}
__device__ __forceinline__ uint32_t pack_bf16x2(float x, float y) {
    __nv_bfloat16 hx = __float2bfloat16(x), hy = __float2bfloat16(y);
    return ((uint32_t)__bfloat16_as_ushort(hy) << 16) | (uint32_t)__bfloat16_as_ushort(hx);
}
__device__ __forceinline__ void cp16(uint32_t dst, const void* src) {
    asm volatile("cp.async.cg.shared.global [%0], [%1], 16;" :: "r"(dst), "l"(src));
}
__device__ __forceinline__ float ex2(float x) {
    float r;
    asm("ex2.approx.f32 %0, %1;" : "=f"(r) : "f"(x));
    return r;
}
#define CP_COMMIT() asm volatile("cp.async.commit_group;" ::: "memory")
#define CP_WAIT1()  asm volatile("cp.async.wait_group 1;" ::: "memory")

// ---------------- fp32 -> bf16 hi/lo split ------------------------------------
__global__ void split_kernel(const float* __restrict__ src,
                             __nv_bfloat16* __restrict__ hi,
                             __nv_bfloat16* __restrict__ lo, int n4)
{
    int i = blockIdx.x * blockDim.x + threadIdx.x;
    if (i >= n4) return;
    float4 v = reinterpret_cast<const float4*>(src)[i];
    float hx = __bfloat162float(__float2bfloat16(v.x));
    float hy = __bfloat162float(__float2bfloat16(v.y));
    float hz = __bfloat162float(__float2bfloat16(v.z));
    float hw = __bfloat162float(__float2bfloat16(v.w));
    reinterpret_cast<uint2*>(hi)[i] =
        make_uint2(pack_bf16x2(v.x, v.y), pack_bf16x2(v.z, v.w));
    reinterpret_cast<uint2*>(lo)[i] =
        make_uint2(pack_bf16x2(v.x - hx, v.y - hy), pack_bf16x2(v.z - hz, v.w - hw));
}

// ====== pipelined bf16 split GEMM, 2-stage cp.async, block 128x64 =============
template<int BN>
__global__ __launch_bounds__(256)
void gemm_bs(const __nv_bfloat16* __restrict__ Ah, const __nv_bfloat16* __restrict__ Al,
             const __nv_bfloat16* __restrict__ Bh, const __nv_bfloat16* __restrict__ Bl,
             float* __restrict__ C0, float* __restrict__ C1,
             float* __restrict__ C2, float* __restrict__ C3,
             int kspan, int lda, int ldb, int ldc)
{
    constexpr int BM = 128, BK = 32;
    constexpr int WN = BN / 2;
    constexpr int NT = WN / 8;
    constexpr int PITCH = BK + 8;
    constexpr int OFF_AH = 0;
    constexpr int OFF_AL = BM*PITCH;
    constexpr int OFF_BH = 2*BM*PITCH;
    constexpr int OFF_BL = 2*BM*PITCH + BN*PITCH;
    constexpr int STAGE  = 2*BM*PITCH + 2*BN*PITCH;

    extern __shared__ __align__(16) uint16_t smem[];
    const uint32_t sbase = smem_u32(smem);

    const int tid  = threadIdx.x;
    const int wid  = tid >> 5;
    const int lane = tid & 31;
    const int warp_m = wid & 3;
    const int warp_n = wid >> 2;
    const int m0 = blockIdx.y * BM;
    const int n0 = blockIdx.x * BN;
    const int kbeg = blockIdx.z * kspan;
    const int kend = kbeg + kspan;
    float* C = (blockIdx.z == 0) ? C0 : (blockIdx.z == 1) ? C1
             : (blockIdx.z == 2) ? C2 : C3;

    const int ld_r = tid >> 2;
    const int ld_c = (tid & 3) << 3;

    float acc[2][NT][4];
    #pragma unroll
    for (int mt = 0; mt < 2; ++mt)
        #pragma unroll
        for (int nt = 0; nt < NT; ++nt)
            #pragma unroll
            for (int j = 0; j < 4; ++j) acc[mt][nt][j] = 0.f;

    const int a_row = (lane & 15);
    const int a_koff = (lane >> 4) << 3;
    const int b_row = ((lane >> 4) << 3) + (lane & 7);
    const int b_koff = ((lane >> 3) & 1) << 3;

    auto load_stage = [&](int s, int k0) {
        uint32_t base = sbase + (uint32_t)(s*STAGE*2);
        #pragma unroll
        for (int i = 0; i < 2; ++i) {
            int r = ld_r + i*64;
            uint32_t so = base + (uint32_t)((r*PITCH + ld_c)*2);
            cp16(so + OFF_AH*2, Ah + (size_t)(m0+r)*lda + k0 + ld_c);
            cp16(so + OFF_AL*2, Al + (size_t)(m0+r)*lda + k0 + ld_c);
            if (i*64 < BN) {
                cp16(so + OFF_BH*2, Bh + (size_t)(n0+r)*ldb + k0 + ld_c);
                cp16(so + OFF_BL*2, Bl + (size_t)(n0+r)*ldb + k0 + ld_c);
            }
        }
    };

    load_stage(0, kbeg);
    CP_COMMIT();

    int buf = 0;
    for (int k0 = kbeg; k0 < kend; k0 += BK) {
        if (k0 + BK < kend) load_stage(buf ^ 1, k0 + BK);
        CP_COMMIT();
        CP_WAIT1();
        __syncthreads();

        const uint32_t stg = sbase + (uint32_t)(buf*STAGE*2);
        #pragma unroll
        for (int kstep = 0; kstep < 2; ++kstep) {
            uint32_t aH[2][4], aL[2][4];
            #pragma unroll
            for (int mt = 0; mt < 2; ++mt) {
                uint32_t off = (uint32_t)(((warp_m*32 + mt*16 + a_row)*PITCH
                                          + kstep*16 + a_koff) * 2);
                ldsm4(aH[mt], stg + OFF_AH*2 + off);
                ldsm4(aL[mt], stg + OFF_AL*2 + off);
            }
            #pragma unroll
            for (int p = 0; p < NT/2; ++p) {
                uint32_t off = (uint32_t)(((warp_n*WN + p*16 + b_row)*PITCH
                                          + kstep*16 + b_koff) * 2);
                uint32_t rH[4], rL[4];
                ldsm4(rH, stg + OFF_BH*2 + off);
                ldsm4(rL, stg + OFF_BL*2 + off);
                #pragma unroll
                for (int mt = 0; mt < 2; ++mt) {
                    mma_bf16(acc[mt][2*p],   aH[mt], rH[0], rH[1]);
                    mma_bf16(acc[mt][2*p],   aH[mt], rL[0], rL[1]);
                    mma_bf16(acc[mt][2*p],   aL[mt], rH[0], rH[1]);
                    mma_bf16(acc[mt][2*p+1], aH[mt], rH[2], rH[3]);
                    mma_bf16(acc[mt][2*p+1], aH[mt], rL[2], rL[3]);
                    mma_bf16(acc[mt][2*p+1], aL[mt], rH[2], rH[3]);
                }
            }
        }
        __syncthreads();
        buf ^= 1;
    }

    #pragma unroll
    for (int mt = 0; mt < 2; ++mt) {
        int r0 = m0 + warp_m*32 + mt*16 + (lane >> 2);
        #pragma unroll
        for (int nt = 0; nt < NT; ++nt) {
            int c0 = n0 + warp_n*WN + nt*8 + ((lane & 3) << 1);
            *reinterpret_cast<float2*>(C + (size_t)r0*ldc + c0) =
                make_float2(acc[mt][nt][0], acc[mt][nt][1]);
            *reinterpret_cast<float2*>(C + (size_t)(r0+8)*ldc + c0) =
                make_float2(acc[mt][nt][2], acc[mt][nt][3]);
        }
    }
}

// ---------- conv+silu, streaming (each xi element read once) -------------------
// grid (32 chunks, 8 batch); 256 threads, thread owns 4 channels; 32 tokens/blk
__global__ __launch_bounds__(256)
void conv_silu_kernel(const float* __restrict__ conv_w,
                      const float* __restrict__ conv_b)
{
    const int b  = blockIdx.y;
    const int t0 = blockIdx.x << 5;
    const int tid = threadIdx.x;
    const int d4 = tid << 2;

    float4 cw[4];
    #pragma unroll
    for (int j = 0; j < 4; ++j)
        cw[j] = reinterpret_cast<const float4*>(conv_w)[d4 + j];
    const float4 bb = reinterpret_cast<const float4*>(conv_b)[tid];

    const float* src = g_xi + (size_t)(b*SEQ)*DINNER + d4;
    float4 x0, x1, x2;
    const float4 z4 = make_float4(0.f,0.f,0.f,0.f);
    x0 = (t0 >= 3) ? *reinterpret_cast<const float4*>(src + (size_t)(t0-3)*DINNER) : z4;
    x1 = (t0 >= 2) ? *reinterpret_cast<const float4*>(src + (size_t)(t0-2)*DINNER) : z4;
    x2 = (t0 >= 1) ? *reinterpret_cast<const float4*>(src + (size_t)(t0-1)*DINNER) : z4;

    #pragma unroll 4
    for (int l = t0; l < t0 + 32; ++l) {
        float4 x3 = *reinterpret_cast<const float4*>(src + (size_t)l*DINNER);
        float4 acc;
        acc.x = bb.x + cw[0].x*x0.x + cw[0].y*x1.x + cw[0].z*x2.x + cw[0].w*x3.x;
        acc.y = bb.y + cw[1].x*x0.y + cw[1].y*x1.y + cw[1].z*x2.y + cw[1].w*x3.y;
        acc.z = bb.z + cw[2].x*x0.z + cw[2].y*x1.z + cw[2].z*x2.z + cw[2].w*x3.z;
        acc.w = bb.w + cw[3].x*x0.w + cw[3].y*x1.w + cw[3].z*x2.w + cw[3].w*x3.w;
        acc.x = acc.x / (1.f + __expf(-acc.x));
        acc.y = acc.y / (1.f + __expf(-acc.y));
        acc.z = acc.z / (1.f + __expf(-acc.z));
        acc.w = acc.w / (1.f + __expf(-acc.w));

        size_t o = (size_t)(b*SEQ + l)*DINNER + d4;
        float hx = __bfloat162float(__float2bfloat16(acc.x));
        float hy = __bfloat162float(__float2bfloat16(acc.y));
        float hz = __bfloat162float(__float2bfloat16(acc.z));
        float hw = __bfloat162float(__float2bfloat16(acc.w));
        *reinterpret_cast<uint2*>(g_xch + o) =
            make_uint2(pack_bf16x2(acc.x, acc.y), pack_bf16x2(acc.z, acc.w));
        *reinterpret_cast<uint2*>(g_xcl + o) =
            make_uint2(pack_bf16x2(acc.x-hx, acc.y-hy), pack_bf16x2(acc.z-hz, acc.w-hw));
        x0 = x1; x1 = x2; x2 = x3;
    }
}

// ---------------- dt only: dt = softplus(dbc[:,:32]@W_dt^T + b_dt) ------------
__global__ __launch_bounds__(256)
void dt_kernel(const float* __restrict__ W_dt, const float* __restrict__ b_dt)
{
    const int c  = blockIdx.x * 256 + threadIdx.x;
    const int m0 = blockIdx.y * 32;
    const int tid = threadIdx.x;

    float w[DTRANK];
    #pragma unroll
    for (int k = 0; k < DTRANK; k += 4) {
        float4 v = *reinterpret_cast<const float4*>(W_dt + (size_t)c*DTRANK + k);
        w[k] = v.x; w[k+1] = v.y; w[k+2] = v.z; w[k+3] = v.w;
    }
    const float bias = b_dt[c];

    __shared__ __align__(16) float s_r[32][36];
    #pragma unroll
    for (int i = 0; i < 4; ++i) {
        int e = tid + i*256;
        int tt = e >> 5, r = e & 31;
        int g = (m0 + tt)*NDBC + r;
        s_r[tt][r] = (g_dbcp[0][g] + g_dbcp[1][g]) + (g_dbcp[2][g] + g_dbcp[3][g]);
    }
    __syncthreads();

    #pragma unroll
    for (int tp = 0; tp < 16; ++tp) {
        const int ta = 2*tp, tb = 2*tp + 1;
        float a0 = bias, a1 = 0.f, a2 = 0.f, a3 = 0.f;
        float b0 = bias, b1 = 0.f, b2 = 0.f, b3 = 0.f;
        #pragma unroll
        for (int k = 0; k < DTRANK; k += 16) {
            float4 ra0 = *reinterpret_cast<const float4*>(&s_r[ta][k]);
            float4 ra1 = *reinterpret_cast<const float4*>(&s_r[ta][k+4]);
            float4 ra2 = *reinterpret_cast<const float4*>(&s_r[ta][k+8]);
            float4 ra3 = *reinterpret_cast<const float4*>(&s_r[ta][k+12]);
            float4 rb0 = *reinterpret_cast<const float4*>(&s_r[tb][k]);
            float4 rb1 = *reinterpret_cast<const float4*>(&s_r[tb][k+4]);
            float4 rb2 = *reinterpret_cast<const float4*>(&s_r[tb][k+8]);
            float4 rb3 = *reinterpret_cast<const float4*>(&s_r[tb][k+12]);
            a0 = fmaf(ra0.x, w[k+0],  a0);  a0 = fmaf(ra0.y, w[k+1],  a0);
            a1 = fmaf(ra0.z, w[k+2],  a1);  a1 = fmaf(ra0.w, w[k+3],  a1);
            a2 = fmaf(ra1.x, w[k+4],  a2);  a2 = fmaf(ra1.y, w[k+5],  a2);
            a3 = fmaf(ra1.z, w[k+6],  a3);  a3 = fmaf(ra1.w, w[k+7],  a3);
            a0 = fmaf(ra2.x, w[k+8],  a0);  a0 = fmaf(ra2.y, w[k+9],  a0);
            a1 = fmaf(ra2.z, w[k+10], a1);  a1 = fmaf(ra2.w, w[k+11], a1);
            a2 = fmaf(ra3.x, w[k+12], a2);  a2 = fmaf(ra3.y, w[k+13], a2);
            a3 = fmaf(ra3.z, w[k+14], a3);  a3 = fmaf(ra3.w, w[k+15], a3);
            b0 = fmaf(rb0.x, w[k+0],  b0);  b0 = fmaf(rb0.y, w[k+1],  b0);
            b1 = fmaf(rb0.z, w[k+2],  b1);  b1 = fmaf(rb0.w, w[k+3],  b1);
            b2 = fmaf(rb1.x, w[k+4],  b2);  b2 = fmaf(rb1.y, w[k+5],  b2);
            b3 = fmaf(rb1.z, w[k+6],  b3);  b3 = fmaf(rb1.w, w[k+7],  b3);
            b0 = fmaf(rb2.x, w[k+8],  b0);  b0 = fmaf(rb2.y, w[k+9],  b0);
            b1 = fmaf(rb2.z, w[k+10], b1);  b1 = fmaf(rb2.w, w[k+11], b1);
            b2 = fmaf(rb3.x, w[k+12], b2);  b2 = fmaf(rb3.y, w[k+13], b2);
            b3 = fmaf(rb3.z, w[k+14], b3);  b3 = fmaf(rb3.w, w[k+15], b3);
        }
        float sa = (a0 + a1) + (a2 + a3);
        float sb = (b0 + b1) + (b2 + b3);
        g_dt[(size_t)(m0 + ta)*DINNER + c] =
            (sa > 15.f) ? sa : __logf(1.f + __expf(sa));
        g_dt[(size_t)(m0 + tb)*DINNER + c] =
            (sb > 15.f) ? sb : __logf(1.f + __expf(sb));
    }
}

// ---------------- selective scan (du computed in staging; fused zlast) --------
__global__ __launch_bounds__(256)
void scan_kernel(const float* __restrict__ A_log,
                 const float* __restrict__ Dv,
                 const float* __restrict__ x,
                 const float* __restrict__ W_in)
{
    const int b     = blockIdx.x >> 6;
    const int dbase = (blockIdx.x & 63) << 4;
    const int tid = threadIdx.x;
    const int dl  = tid >> 4;
    const int s   = tid & 15;
    const int d   = dbase + dl;

    __shared__ float s_z[16];
    __shared__ __align__(16) float s_dtT[16][68];
    __shared__ __align__(16) float s_duT[16][68];
    __shared__ __align__(16) float s_BT [16][68];

    // fused zlast
    {
        const float* xr = x + ((size_t)b*SEQ + (SEQ-1))*DMODEL + s*32;
        const float* wr = W_in + (size_t)(DINNER + dbase + dl)*DMODEL + s*32;
        float a0 = 0.f, a1 = 0.f, a2 = 0.f, a3 = 0.f;
        #pragma unroll
        for (int k = 0; k < 32; k += 4) {
            float4 xv = *reinterpret_cast<const float4*>(xr + k);
            float4 wv = *reinterpret_cast<const float4*>(wr + k);
            a0 = fmaf(xv.x, wv.x, a0);
            a1 = fmaf(xv.y, wv.y, a1);
            a2 = fmaf(xv.z, wv.z, a2);
            a3 = fmaf(xv.w, wv.w, a3);
        }
        float acc = (a0 + a1) + (a2 + a3);
        #pragma unroll
        for (int off = 8; off; off >>= 1)
            acc += __shfl_down_sync(0xffffffffu, acc, off, 16);
        if (s == 0) s_z[dl] = acc;
    }

    const float A2_s = -__expf(A_log[d*DSTATE + s]) * 1.44269504f;
    float h = 0.f;

    for (int t0 = 0; t0 < SEQ; t0 += 64) {
        __syncthreads();
        #pragma unroll
        for (int i = 0; i < 4; ++i) {
            int idx = tid + i*256;
            int tt = idx >> 4, c = idx & 15;
            int m = b*SEQ + t0 + tt;
            size_t o = (size_t)m*DINNER + dbase + c;
            float dt = g_dt[o];
            float u  = __bfloat162float(g_xch[o]) + __bfloat162float(g_xcl[o]);
            s_dtT[c][tt] = dt;
            s_duT[c][tt] = dt * u;
            int g = m*NDBC + DTRANK + c;
            s_BT[c][tt] = (g_dbcp[0][g] + g_dbcp[1][g])
                        + (g_dbcp[2][g] + g_dbcp[3][g]);
        }
        __syncthreads();
        #pragma unroll
        for (int t4 = 0; t4 < 16; ++t4) {
            float4 dt4 = *reinterpret_cast<float4*>(&s_dtT[dl][t4*4]);
            float4 du4 = *reinterpret_cast<float4*>(&s_duT[dl][t4*4]);
            float4 B4  = *reinterpret_cast<float4*>(&s_BT [s][t4*4]);
            h = fmaf(ex2(dt4.x * A2_s), h, du4.x * B4.x);
            h = fmaf(ex2(dt4.y * A2_s), h, du4.y * B4.y);
            h = fmaf(ex2(dt4.z * A2_s), h, du4.z * B4.z);
            h = fmaf(ex2(dt4.w * A2_s), h, du4.w * B4.w);
        }
    }

    const int mlast = b*SEQ + (SEQ-1);
    int gc = mlast*NDBC + DTRANK + DSTATE + s;
    float Cv = (g_dbcp[0][gc] + g_dbcp[1][gc]) + (g_dbcp[2][gc] + g_dbcp[3][gc]);
    float y = h * Cv;
    #pragma unroll
    for (int off = 8; off; off >>= 1) y += __shfl_down_sync(0xffffffffu, y, off, 16);
    if (s == 0) {
        size_t o = (size_t)mlast*DINNER + d;
        float ul = __bfloat162float(g_xch[o]) + __bfloat162float(g_xcl[o]);
        float zl = s_z[dl];
        float silu_z = zl / (1.f + __expf(-zl));
        g_ylast[b*DINNER + d] = (y + Dv[d]*ul) * silu_z;
    }
}

// ---------------- out projection: last = ylast @ W_out^T ----------------------
__global__ __launch_bounds__(256)
void outproj_kernel(const float* __restrict__ W_out)
{
    const int j = blockIdx.x;
    __shared__ float w[DINNER];
    for (int i = threadIdx.x; i < DINNER; i += 256)
        w[i] = W_out[(size_t)j*DINNER + i];
    __syncthreads();
    const int b = threadIdx.x >> 5;
    const int lane = threadIdx.x & 31;
    float acc = 0.f;
    #pragma unroll 8
    for (int k = lane; k < DINNER; k += 32)
        acc = fmaf(g_ylast[b*DINNER + k], w[k], acc);
    #pragma unroll
    for (int off = 16; off; off >>= 1) acc += __shfl_down_sync(0xffffffffu, acc, off);
    if (lane == 0) g_last[b*DMODEL + j] = acc;
}

// ---------------- layernorm ----------------------------------------------------
__global__ void ln_kernel(const float* __restrict__ ln_g,
                          const float* __restrict__ ln_b)
{
    const int b = blockIdx.x;
    const int j = threadIdx.x;
    __shared__ float rbuf[DMODEL];
    float v = g_last[b*DMODEL + j];
    rbuf[j] = v;
    __syncthreads();
    #pragma unroll
    for (int st = 256; st > 0; st >>= 1) {
        if (j < st) rbuf[j] += rbuf[j + st];
        __syncthreads();
    }
    float mu = rbuf[0] / (float)DMODEL;
    __syncthreads();
    float diff = v - mu;
    rbuf[j] = diff * diff;
    __syncthreads();
    #pragma unroll
    for (int st = 256; st > 0; st >>= 1) {
        if (j < st) rbuf[j] += rbuf[j + st];
        __syncthreads();
    }
    float rstd = rsqrtf(rbuf[0] / (float)DMODEL + 1e-5f);
    g_lastn[b*DMODEL + j] = diff * rstd * ln_g[j] + ln_b[j];
}

// ---------------- head: out = lastn @ head_W^T + head_b ------------------------
__global__ __launch_bounds__(256)
void head_kernel(const float* __restrict__ head_W,
                 const float* __restrict__ head_b,
                 float* __restrict__ out)
{
    const int j = blockIdx.x;
    __shared__ float w[DMODEL];
    for (int i = threadIdx.x; i < DMODEL; i += 256)
        w[i] = head_W[(size_t)j*DMODEL + i];
    __syncthreads();
    const int b = threadIdx.x >> 5;
    const int lane = threadIdx.x & 31;
    float acc = 0.f;
    #pragma unroll 4
    for (int k = lane; k < DMODEL; k += 32)
        acc = fmaf(g_lastn[b*DMODEL + k], w[k], acc);
    #pragma unroll
    for (int off = 16; off; off >>= 1) acc += __shfl_down_sync(0xffffffffu, acc, off);
    if (lane == 0) out[b*DMODEL + j] = acc + head_b[j];
}

// ---------------- launch --------------------------------------------------------
extern "C" void kernel_launch(void* const* d_in, const int* in_sizes, int n_in,
                              void* d_out, int out_size)
{
    const float* x      = (const float*)d_in[0];
    const float* W_in   = (const float*)d_in[1];
    const float* conv_w = (const float*)d_in[2];
    const float* conv_b = (const float*)d_in[3];
    const float* W_x    = (const float*)d_in[4];
    const float* W_dt   = (const float*)d_in[5];
    const float* b_dt   = (const float*)d_in[6];
    const float* A_log  = (const float*)d_in[7];
    const float* Dv     = (const float*)d_in[8];
    const float* W_out  = (const float*)d_in[9];
    const float* ln_g   = (const float*)d_in[10];
    const float* ln_b   = (const float*)d_in[11];
    const float* head_W = (const float*)d_in[12];
    const float* head_b = (const float*)d_in[13];
    float* out = (float*)d_out;

    float *xi, *dbcp0, *dbcp1, *dbcp2, *dbcp3;
    cudaGetSymbolAddress((void**)&xi, g_xi);
    cudaGetSymbolAddress((void**)&dbcp0, g_dbcp);
    dbcp1 = dbcp0 + MTOK*NDBC;
    dbcp2 = dbcp1 + MTOK*NDBC;
    dbcp3 = dbcp2 + MTOK*NDBC;
    __nv_bfloat16 *xh, *xl, *wih, *wil, *wxh, *wxl, *xch, *xcl;
    cudaGetSymbolAddress((void**)&xh,  g_xh);
    cudaGetSymbolAddress((void**)&xl,  g_xl);
    cudaGetSymbolAddress((void**)&wih, g_wih);
    cudaGetSymbolAddress((void**)&wil, g_wil);
    cudaGetSymbolAddress((void**)&wxh, g_wxh);
    cudaGetSymbolAddress((void**)&wxl, g_wxl);
    cudaGetSymbolAddress((void**)&xch, g_xch);
    cudaGetSymbolAddress((void**)&xcl, g_xcl);

    const int SMEM2 = (2*128*40 + 2*64*40) * 2 * 2;   // 61440
    cudaFuncSetAttribute((const void*)gemm_bs<64>,
                         cudaFuncAttributeMaxDynamicSharedMemorySize, SMEM2);

    // #0-#2: splits
    split_kernel<<<(MTOK*DMODEL/4 + 255)/256, 256>>>(x, xh, xl, MTOK*DMODEL/4);
    split_kernel<<<(DINNER*DMODEL/4 + 255)/256, 256>>>(W_in, wih, wil, DINNER*DMODEL/4);
    split_kernel<<<(NDBC*DINNER/4 + 255)/256, 256>>>(W_x, wxh, wxl, NDBC*DINNER/4);

    // #3 (ncu target): K1 plain — xi = x @ W_in[:1024].T (unfused; round-16 A/B
    // showed the conv epilogue costs ~85us vs ~15us for a separate conv pass)
    gemm_bs<64><<<dim3(DINNER/64, MTOK/128, 1), 256, SMEM2>>>(
        xh, xl, wih, wil, xi, xi, xi, xi, DMODEL, DMODEL, DMODEL, DINNER);

    // #4: streaming conv + silu -> xch/xcl
    conv_silu_kernel<<<dim3(32, 8), 256>>>(conv_w, conv_b);

    // #5: K3: dbc partials = xc @ W_x.T, K split x4
    gemm_bs<64><<<dim3(1, MTOK/128, 4), 256, SMEM2>>>(
        xch, xcl, wxh, wxl, dbcp0, dbcp1, dbcp2, dbcp3,
        DINNER/4, DINNER, DINNER, NDBC);

    // #6: dt precompute
    dt_kernel<<<dim3(DINNER/256, MTOK/32), 256>>>(W_dt, b_dt);

    // #7: selective scan
    scan_kernel<<<BATCH * (DINNER/16), 256>>>(A_log, Dv, x, W_in);

    // #8-#10: out projection, layernorm, head
    outproj_kernel<<<DMODEL, 256>>>(W_out);
    ln_kernel<<<BATCH, DMODEL>>>(ln_g, ln_b);
    head_kernel<<<DMODEL, 256>>>(head_W, head_b, out);
}